// round 9
// baseline (speedup 1.0000x reference)
#include <cuda_runtime.h>
#include <cuda_bf16.h>
#include <math.h>
#include <stdint.h>

// ---------------- problem constants ----------------
#define T_SEQ   2048
#define D_MODEL 3072
#define N_HEADS 16
#define K_HEADS 8
#define HDIM    256
#define WINDOW  1024
#define SOFT_CAP 50.0f
#define EPS 1e-6f

// ---------------- scratch (static device globals) ----------------
__device__ float g_qkv[(size_t)T_SEQ * 32 * HDIM];          // [t][slot][h] q0-15,k16-23,v24-31
__device__ __nv_bfloat16 g_xh [(size_t)T_SEQ * D_MODEL];
__device__ __nv_bfloat16 g_xl [(size_t)T_SEQ * D_MODEL];
__device__ __nv_bfloat16 g_qh [(size_t)T_SEQ * N_HEADS * HDIM];
__device__ __nv_bfloat16 g_ql [(size_t)T_SEQ * N_HEADS * HDIM];
__device__ __nv_bfloat16 g_kvh[(size_t)T_SEQ * 16 * HDIM];
__device__ __nv_bfloat16 g_kvl[(size_t)T_SEQ * 16 * HDIM];
__device__ __nv_bfloat16 g_wallh[(size_t)32 * HDIM * D_MODEL];  // [slot][h][d] K-major
__device__ __nv_bfloat16 g_walll[(size_t)32 * HDIM * D_MODEL];
__device__ __nv_bfloat16 g_woh [(size_t)D_MODEL * N_HEADS * HDIM];
__device__ __nv_bfloat16 g_wol [(size_t)D_MODEL * N_HEADS * HDIM];
__device__ __nv_bfloat16 g_ench[(size_t)T_SEQ * N_HEADS * HDIM];
__device__ __nv_bfloat16 g_encl[(size_t)T_SEQ * N_HEADS * HDIM];

// ---------------- low-level helpers ----------------
__device__ __forceinline__ uint32_t smem_u32(const void* p) {
    uint32_t a;
    asm("{ .reg .u64 t; cvta.to.shared.u64 t, %1; cvt.u32.u64 %0, t; }" : "=r"(a) : "l"(p));
    return a;
}
__device__ __forceinline__ void cp_async16(uint32_t dst, const void* src) {
    asm volatile("cp.async.cg.shared.global [%0], [%1], 16;" :: "r"(dst), "l"(src));
}
__device__ __forceinline__ void cp_commit() { asm volatile("cp.async.commit_group;"); }
__device__ __forceinline__ void cp_wait1()  { asm volatile("cp.async.wait_group 1;"); }
__device__ __forceinline__ void cp_wait0()  { asm volatile("cp.async.wait_group 0;"); }

__device__ __forceinline__ void ldsm_x4(uint32_t& r0, uint32_t& r1, uint32_t& r2, uint32_t& r3,
                                        uint32_t addr) {
    asm volatile("ldmatrix.sync.aligned.m8n8.x4.shared.b16 {%0,%1,%2,%3}, [%4];"
                 : "=r"(r0), "=r"(r1), "=r"(r2), "=r"(r3) : "r"(addr));
}
__device__ __forceinline__ void ldsm_x4t(uint32_t& r0, uint32_t& r1, uint32_t& r2, uint32_t& r3,
                                         uint32_t addr) {
    asm volatile("ldmatrix.sync.aligned.m8n8.x4.trans.shared.b16 {%0,%1,%2,%3}, [%4];"
                 : "=r"(r0), "=r"(r1), "=r"(r2), "=r"(r3) : "r"(addr));
}
__device__ __forceinline__ void mma_bf16(float* c, const uint32_t* a, const uint32_t* b) {
    asm volatile("mma.sync.aligned.m16n8k16.row.col.f32.bf16.bf16.f32 "
                 "{%0,%1,%2,%3},{%4,%5,%6,%7},{%8,%9},{%0,%1,%2,%3};"
                 : "+f"(c[0]), "+f"(c[1]), "+f"(c[2]), "+f"(c[3])
                 : "r"(a[0]), "r"(a[1]), "r"(a[2]), "r"(a[3]), "r"(b[0]), "r"(b[1]));
}
__device__ __forceinline__ void split_bf16(float x, __nv_bfloat16& h, __nv_bfloat16& l) {
    h = __float2bfloat16(x);
    l = __float2bfloat16(x - __bfloat162float(h));
}

// ================= split-bf16 GEMM: persistent, 2-stage, 2 CTAs/SM =================
// MT=64, NT=128: 8 warps 1Mx8N (warp 64x16, JW=2).
// A planes [M][K]; B planes flat [N_total][K] K-major; C fp32 row-major.
// Grid-stride over tiles: tile -> (mi = tile/ntilesN, ni = tile%ntilesN).
#define LDHB 80                       // smem row bytes (40 halves: 64B data + pad)
#define GMT 64
#define GNT 128
#define G_APL (GMT * LDHB)            // 5120
#define G_BPL (GNT * LDHB)            // 10240
#define G_STAGE (2 * G_APL + 2 * G_BPL)   // 30720
#define GEMM2_SMEM (2 * G_STAGE)          // 61440

__global__ __launch_bounds__(256, 2) void gemm2_bf16_kernel(
    const __nv_bfloat16* __restrict__ Ah, const __nv_bfloat16* __restrict__ Al,
    const __nv_bfloat16* __restrict__ Bh, const __nv_bfloat16* __restrict__ Bl,
    float* __restrict__ C, int Kdim, int ldc, int ntilesN, int ntiles)
{
    extern __shared__ char smem[];
    const uint32_t sbase = smem_u32(smem);
    const int tid = threadIdx.x;
    const int wid = tid >> 5, lane = tid & 31;
    const int wn = wid;                         // 8 N-warps, warp tile 64x16
    const int g = lane >> 2, t4 = lane & 3;
    const int NK = Kdim / 32;

    // lane-derived fragment offsets (tile-independent)
    const int arow = (lane & 7) + ((lane >> 3) & 1) * 8;
    const int akof = ((lane >> 4) & 1) * 8;
    const int brow = wn * 16 + (lane & 7) + ((lane >> 4) & 1) * 8;
    const int bkof = ((lane >> 3) & 1) * 8;

    for (int tile = blockIdx.x; tile < ntiles; tile += gridDim.x) {
        const int m0 = (tile / ntilesN) * GMT;
        const int n0 = (tile % ntilesN) * GNT;
        const __nv_bfloat16* Ahm = Ah + (size_t)m0 * Kdim;
        const __nv_bfloat16* Alm = Al + (size_t)m0 * Kdim;
        const __nv_bfloat16* Bhz = Bh + (size_t)n0 * Kdim;
        const __nv_bfloat16* Blz = Bl + (size_t)n0 * Kdim;

        auto issue_stage = [&](int s, int kt) {
            const int k0 = kt * 32;
            const uint32_t stg = sbase + s * G_STAGE;
            {   // A: 64 rows x 4 chunks = 256 chunks, 1 per thread
                int r = tid >> 2, c = tid & 3;
                size_t goff = (size_t)r * Kdim + k0 + c * 8;
                uint32_t d = stg + r * LDHB + c * 16;
                cp_async16(d,         Ahm + goff);
                cp_async16(d + G_APL, Alm + goff);
            }
            #pragma unroll
            for (int i = 0; i < 2; i++) {   // B: 128 rows x 4 chunks
                int idx = tid + i * 256;
                int r = idx >> 2, c = idx & 3;
                size_t goff = (size_t)r * Kdim + k0 + c * 8;
                uint32_t d = stg + 2 * G_APL + r * LDHB + c * 16;
                cp_async16(d,         Bhz + goff);
                cp_async16(d + G_BPL, Blz + goff);
            }
        };

        float acc[4][2][4];
        #pragma unroll
        for (int i = 0; i < 4; i++)
            #pragma unroll
            for (int j = 0; j < 2; j++)
                #pragma unroll
                for (int r = 0; r < 4; r++) acc[i][j][r] = 0.f;

        issue_stage(0, 0); cp_commit();
        issue_stage(1, 1); cp_commit();

        for (int kt = 0; kt < NK; kt++) {
            if (kt >= NK - 1) cp_wait0(); else cp_wait1();
            __syncthreads();

            const uint32_t st = sbase + (kt & 1) * G_STAGE;
            #pragma unroll
            for (int ks = 0; ks < 2; ks++) {
                uint32_t ah[4][4], al[4][4];
                #pragma unroll
                for (int i = 0; i < 4; i++) {
                    uint32_t ad = st + (arow + i * 16) * LDHB + (ks * 16 + akof) * 2;
                    ldsm_x4(ah[i][0], ah[i][1], ah[i][2], ah[i][3], ad);
                    ldsm_x4(al[i][0], al[i][1], al[i][2], al[i][3], ad + G_APL);
                }
                uint32_t bd = st + 2 * G_APL + brow * LDHB + (ks * 16 + bkof) * 2;
                uint32_t bh[4], bl[4];
                ldsm_x4(bh[0], bh[1], bh[2], bh[3], bd);
                ldsm_x4(bl[0], bl[1], bl[2], bl[3], bd + G_BPL);
                #pragma unroll
                for (int i = 0; i < 4; i++) {
                    #pragma unroll
                    for (int jj = 0; jj < 2; jj++) {
                        mma_bf16(acc[i][jj], ah[i], bh + 2 * jj);
                        mma_bf16(acc[i][jj], ah[i], bl + 2 * jj);
                        mma_bf16(acc[i][jj], al[i], bh + 2 * jj);
                    }
                }
            }

            __syncthreads();                 // all warps done with this stage
            if (kt + 2 < NK) { issue_stage(kt & 1, kt + 2); cp_commit(); }
        }

        // epilogue
        #pragma unroll
        for (int i = 0; i < 4; i++) {
            const int r0 = m0 + i * 16 + g;
            #pragma unroll
            for (int j = 0; j < 2; j++) {
                const int c0 = n0 + wn * 16 + j * 8 + t4 * 2;
                *reinterpret_cast<float2*>(&C[(size_t)r0 * ldc + c0]) =
                    make_float2(acc[i][j][0], acc[i][j][1]);
                *reinterpret_cast<float2*>(&C[(size_t)(r0 + 8) * ldc + c0]) =
                    make_float2(acc[i][j][2], acc[i][j][3]);
            }
        }
        __syncthreads();                     // smem free before next tile's prologue
    }
}

// ================= x -> bf16 hi/lo planes =================
__global__ __launch_bounds__(256) void convert_x_kernel(const float* __restrict__ x)
{
    size_t i = ((size_t)blockIdx.x * 256 + threadIdx.x) * 4;
    float4 v = *reinterpret_cast<const float4*>(x + i);
    __nv_bfloat16 h[4], l[4];
    split_bf16(v.x, h[0], l[0]); split_bf16(v.y, h[1], l[1]);
    split_bf16(v.z, h[2], l[2]); split_bf16(v.w, h[3], l[3]);
    *reinterpret_cast<__nv_bfloat162*>(g_xh + i)     = __nv_bfloat162(h[0], h[1]);
    *reinterpret_cast<__nv_bfloat162*>(g_xh + i + 2) = __nv_bfloat162(h[2], h[3]);
    *reinterpret_cast<__nv_bfloat162*>(g_xl + i)     = __nv_bfloat162(l[0], l[1]);
    *reinterpret_cast<__nv_bfloat162*>(g_xl + i + 2) = __nv_bfloat162(l[2], l[3]);
}

// ================= transpose + convert: [z][R][C] fp32 -> [z][C][R] bf16 hi/lo =================
__global__ __launch_bounds__(256) void transpose_conv_kernel(
    const float* __restrict__ in, __nv_bfloat16* __restrict__ outh,
    __nv_bfloat16* __restrict__ outl, int R, int C)
{
    __shared__ float t[32][33];
    size_t zo = (size_t)blockIdx.z * R * C;
    int c0 = blockIdx.x * 32, r0 = blockIdx.y * 32;
    int tx = threadIdx.x & 31, ty = threadIdx.x >> 5;
    #pragma unroll
    for (int i = 0; i < 32; i += 8)
        t[ty + i][tx] = in[zo + (size_t)(r0 + ty + i) * C + c0 + tx];
    __syncthreads();
    #pragma unroll
    for (int i = 0; i < 32; i += 8) {
        float v = t[tx][ty + i];
        __nv_bfloat16 h, l;
        split_bf16(v, h, l);
        size_t o = zo + (size_t)(c0 + ty + i) * R + r0 + tx;
        outh[o] = h;
        outl[o] = l;
    }
}

// ================= fused RMS-norm (+scale) (+RoPE) over all 32 slots =================
__device__ __forceinline__ void rope_apply(float v[8], int lane, int pos)
{
    #pragma unroll
    for (int j = 0; j < 4; j++) {
        int hh = lane + 32 * j;
        float ts = powf(10000.0f, (float)hh * (1.0f / 128.0f));
        float arg = (float)pos / ts;
        float sn, cs;
        sincosf(arg, &sn, &cs);
        float f = v[j], s = v[j + 4];
        v[j]     = f * cs - s * sn;
        v[j + 4] = s * cs + f * sn;
    }
}

__global__ __launch_bounds__(256) void norm_rope_all_kernel(const float* __restrict__ qscale,
                                                            const float* __restrict__ kscale,
                                                            const int* __restrict__ segpos)
{
    int row  = blockIdx.x * 8 + (threadIdx.x >> 5);   // 0..T*32-1
    int lane = threadIdx.x & 31;
    int t    = row >> 5;
    int slot = row & 31;                               // 0-15 q, 16-23 k, 24-31 v
    const float* p = g_qkv + (size_t)row * HDIM;

    float v[8]; float ss = 0.f;
    #pragma unroll
    for (int j = 0; j < 8; j++) { v[j] = p[lane + 32 * j]; ss += v[j] * v[j]; }
    #pragma unroll
    for (int o = 16; o > 0; o >>= 1) ss += __shfl_xor_sync(0xffffffffu, ss, o);
    float rstd = rsqrtf(ss * (1.0f / 256.0f) + EPS);

    if (slot < 16) {
        #pragma unroll
        for (int j = 0; j < 8; j++) {
            int h = lane + 32 * j;
            v[j] = v[j] * rstd * (1.0f + qscale[h]);
        }
        rope_apply(v, lane, segpos[t]);
        #pragma unroll
        for (int j = 0; j < 8; j++) {
            int h = lane + 32 * j;
            __nv_bfloat16 hh, ll;
            split_bf16(v[j], hh, ll);
            size_t o = ((size_t)t * 16 + slot) * HDIM + h;
            g_qh[o] = hh; g_ql[o] = ll;
        }
    } else if (slot < 24) {
        #pragma unroll
        for (int j = 0; j < 8; j++) {
            int h = lane + 32 * j;
            v[j] = v[j] * rstd * (1.0f + kscale[h]);
        }
        rope_apply(v, lane, segpos[t]);
        #pragma unroll
        for (int j = 0; j < 8; j++) {
            int h = lane + 32 * j;
            __nv_bfloat16 hh, ll;
            split_bf16(v[j], hh, ll);
            size_t o = ((size_t)t * 16 + (slot - 16)) * HDIM + h;
            g_kvh[o] = hh; g_kvl[o] = ll;
        }
    } else {
        #pragma unroll
        for (int j = 0; j < 8; j++) {
            int h = lane + 32 * j;
            float vv = v[j] * rstd;
            __nv_bfloat16 hh, ll;
            split_bf16(vv, hh, ll);
            size_t o = ((size_t)t * 16 + (slot - 24) + 8) * HDIM + h;
            g_kvh[o] = hh; g_kvl[o] = ll;
        }
    }
}

// ================= tensor-core flash attention (unchanged R6 winner) =================
#define SROWB 528
#define QPL 33792
#define KPL 16896
#define PROWB 80
#define PPL (64 * PROWB)
#define ATTN_SMEM (2 * QPL + 4 * KPL + 2 * PPL + 1024)

__global__ __launch_bounds__(256, 1) void attn_mma_kernel()
{
    extern __shared__ char smc[];
    const uint32_t sb = smem_u32(smc);
    const int tid = threadIdx.x;
    const int wid = tid >> 5, lane = tid & 31;
    const int t0 = blockIdx.x * 64;
    const int n  = blockIdx.y;
    const int hp = n >> 1;
    const int wr = wid & 3, wc = wid >> 2;
    const int R  = wr * 16;
    const int g = lane >> 2, t4 = lane & 3;

    const uint32_t sQh = sb, sQl = sb + QPL;
    const uint32_t sKh = sb + 2 * QPL;
    const uint32_t sKl = sKh + KPL;
    const uint32_t sVh = sKh + 2 * KPL;
    const uint32_t sVl = sKh + 3 * KPL;
    const uint32_t sPh = sb + 2 * QPL + 4 * KPL;
    const uint32_t sPl = sPh + PPL;
    float* redmax = reinterpret_cast<float*>(smc + 2 * QPL + 4 * KPL + 2 * PPL);
    float* redsum = redmax + 128;

    #pragma unroll
    for (int i = 0; i < 16; i++) {
        int idx = tid + i * 256;
        int pl = idx >> 11;
        int r = (idx >> 5) & 63, c = idx & 31;
        const __nv_bfloat16* src = (pl ? g_ql : g_qh) +
            ((size_t)(t0 + r) * 16 + n) * 256 + c * 8;
        cp_async16(sb + pl * QPL + r * SROWB + c * 16, src);
    }
    cp_commit();

    auto issue_K = [&](int sc0) {
        #pragma unroll
        for (int i = 0; i < 8; i++) {
            int idx = tid + i * 256;
            int pl = idx >> 10;
            int r = (idx >> 5) & 31, c = idx & 31;
            const __nv_bfloat16* src = (pl ? g_kvl : g_kvh) +
                ((size_t)(sc0 + r) * 16 + hp) * 256 + c * 8;
            cp_async16(sKh + pl * KPL + r * SROWB + c * 16, src);
        }
    };
    auto issue_V = [&](int sc0) {
        #pragma unroll
        for (int i = 0; i < 8; i++) {
            int idx = tid + i * 256;
            int pl = idx >> 10;
            int r = (idx >> 5) & 31, c = idx & 31;
            const __nv_bfloat16* src = (pl ? g_kvl : g_kvh) +
                ((size_t)(sc0 + r) * 16 + 8 + hp) * 256 + c * 8;
            cp_async16(sVh + pl * KPL + r * SROWB + c * 16, src);
        }
    };

    float o[16][4];
    #pragma unroll
    for (int i = 0; i < 16; i++)
        #pragma unroll
        for (int c = 0; c < 4; c++) o[i][c] = 0.f;
    float m2[2] = {-1e29f, -1e29f}, l2[2] = {0.f, 0.f};

    int s_lo = t0 - (WINDOW - 1); if (s_lo < 0) s_lo = 0; s_lo &= ~31;

    const int aoff  = (R + (lane & 7) + ((lane >> 3) & 1) * 8) * SROWB + ((lane >> 4) & 1) * 16;
    const int koff  = (((lane >> 4) & 1) * 8 + (lane & 7)) * SROWB + ((lane >> 3) & 1) * 16
                      + wc * 16 * SROWB;
    const int voff  = (((lane >> 3) & 1) * 8 + (lane & 7)) * SROWB + ((lane >> 4) & 1) * 16
                      + wc * 256;
    const int aoffP = (R + (lane & 7) + ((lane >> 3) & 1) * 8) * PROWB + ((lane >> 4) & 1) * 16;
    const int tq0 = t0 + R + g, tq1 = tq0 + 8;

    issue_K(s_lo); cp_commit();
    issue_V(s_lo); cp_commit();
    asm volatile("cp.async.wait_group 1;");
    __syncthreads();

    for (int sc0 = s_lo; sc0 <= t0 + 63; sc0 += 32) {
        const bool has_next = (sc0 + 32 <= t0 + 63);

        float s[2][4];
        #pragma unroll
        for (int j = 0; j < 2; j++)
            #pragma unroll
            for (int c = 0; c < 4; c++) s[j][c] = 0.f;

        #pragma unroll 4
        for (int hs = 0; hs < 16; hs++) {
            uint32_t qh[4], ql[4], kh[4], kl[4];
            ldsm_x4(qh[0], qh[1], qh[2], qh[3], sQh + aoff + hs * 32);
            ldsm_x4(ql[0], ql[1], ql[2], ql[3], sQl + aoff + hs * 32);
            ldsm_x4(kh[0], kh[1], kh[2], kh[3], sKh + koff + hs * 32);
            ldsm_x4(kl[0], kl[1], kl[2], kl[3], sKl + koff + hs * 32);
            mma_bf16(s[0], qh, kh); mma_bf16(s[0], qh, kl); mma_bf16(s[0], ql, kh);
            mma_bf16(s[1], qh, kh + 2); mma_bf16(s[1], qh, kl + 2); mma_bf16(s[1], ql, kh + 2);
        }

        #pragma unroll
        for (int j = 0; j < 2; j++)
            #pragma unroll
            for (int c = 0; c < 4; c++) {
                int tq = (c >> 1) ? tq1 : tq0;
                int sk = sc0 + wc * 16 + j * 8 + 2 * t4 + (c & 1);
                float xx = s[j][c] * (1.0f / SOFT_CAP);
                xx = fminf(fmaxf(xx, -10.f), 10.f);
                float e = __expf(2.0f * xx);
                float val = SOFT_CAP * __fdividef(e - 1.0f, e + 1.0f);
                bool ok = (sk <= tq) && (sk > tq - WINDOW);
                s[j][c] = ok ? val : -1e30f;
            }

        float mx0 = fmaxf(fmaxf(s[0][0], s[0][1]), fmaxf(s[1][0], s[1][1]));
        float mx1 = fmaxf(fmaxf(s[0][2], s[0][3]), fmaxf(s[1][2], s[1][3]));
        mx0 = fmaxf(mx0, __shfl_xor_sync(0xffffffffu, mx0, 1));
        mx0 = fmaxf(mx0, __shfl_xor_sync(0xffffffffu, mx0, 2));
        mx1 = fmaxf(mx1, __shfl_xor_sync(0xffffffffu, mx1, 1));
        mx1 = fmaxf(mx1, __shfl_xor_sync(0xffffffffu, mx1, 2));
        if (t4 == 0) {
            redmax[wc * 64 + R + g] = mx0;
            redmax[wc * 64 + R + g + 8] = mx1;
        }
        __syncthreads();

        if (has_next) issue_K(sc0 + 32);
        cp_commit();

        float cm0 = fmaxf(mx0, redmax[(1 - wc) * 64 + R + g]);
        float cm1 = fmaxf(mx1, redmax[(1 - wc) * 64 + R + g + 8]);
        float mn0 = fmaxf(m2[0], cm0), mn1 = fmaxf(m2[1], cm1);
        float a0 = __expf(m2[0] - mn0), a1 = __expf(m2[1] - mn1);
        m2[0] = mn0; m2[1] = mn1;

        float sum0 = 0.f, sum1 = 0.f;
        #pragma unroll
        for (int j = 0; j < 2; j++) {
            s[j][0] = __expf(s[j][0] - mn0); sum0 += s[j][0];
            s[j][1] = __expf(s[j][1] - mn0); sum0 += s[j][1];
            s[j][2] = __expf(s[j][2] - mn1); sum1 += s[j][2];
            s[j][3] = __expf(s[j][3] - mn1); sum1 += s[j][3];
        }
        sum0 += __shfl_xor_sync(0xffffffffu, sum0, 1);
        sum0 += __shfl_xor_sync(0xffffffffu, sum0, 2);
        sum1 += __shfl_xor_sync(0xffffffffu, sum1, 1);
        sum1 += __shfl_xor_sync(0xffffffffu, sum1, 2);
        if (t4 == 0) {
            redsum[wc * 64 + R + g] = sum0;
            redsum[wc * 64 + R + g + 8] = sum1;
        }

        #pragma unroll
        for (int j = 0; j < 2; j++) {
            int kcol = wc * 16 + j * 8 + 2 * t4;
            __nv_bfloat16 h0, l0, h1, l1;
            split_bf16(s[j][0], h0, l0); split_bf16(s[j][1], h1, l1);
            *reinterpret_cast<__nv_bfloat162*>(smc + (sPh - sb) + (R + g) * PROWB + kcol * 2) =
                __nv_bfloat162(h0, h1);
            *reinterpret_cast<__nv_bfloat162*>(smc + (sPl - sb) + (R + g) * PROWB + kcol * 2) =
                __nv_bfloat162(l0, l1);
            split_bf16(s[j][2], h0, l0); split_bf16(s[j][3], h1, l1);
            *reinterpret_cast<__nv_bfloat162*>(smc + (sPh - sb) + (R + g + 8) * PROWB + kcol * 2) =
                __nv_bfloat162(h0, h1);
            *reinterpret_cast<__nv_bfloat162*>(smc + (sPl - sb) + (R + g + 8) * PROWB + kcol * 2) =
                __nv_bfloat162(l0, l1);
        }

        cp_wait1();
        __syncthreads();

        l2[0] = l2[0] * a0 + sum0 + redsum[(1 - wc) * 64 + R + g];
        l2[1] = l2[1] * a1 + sum1 + redsum[(1 - wc) * 64 + R + g + 8];

        if (a0 != 1.f || a1 != 1.f) {
            #pragma unroll
            for (int i = 0; i < 16; i++) {
                o[i][0] *= a0; o[i][1] *= a0;
                o[i][2] *= a1; o[i][3] *= a1;
            }
        }

        #pragma unroll
        for (int ks = 0; ks < 2; ks++) {
            uint32_t ph[4], pl4[4];
            ldsm_x4(ph[0], ph[1], ph[2], ph[3], sPh + aoffP + ks * 32);
            ldsm_x4(pl4[0], pl4[1], pl4[2], pl4[3], sPl + aoffP + ks * 32);
            #pragma unroll
            for (int u = 0; u < 8; u++) {
                uint32_t vh[4], vl[4];
                uint32_t va = sVh + voff + ks * 16 * SROWB + u * 32;
                ldsm_x4t(vh[0], vh[1], vh[2], vh[3], va);
                ldsm_x4t(vl[0], vl[1], vl[2], vl[3], va + KPL);
                mma_bf16(o[2 * u], ph, vh);     mma_bf16(o[2 * u], ph, vl);
                mma_bf16(o[2 * u], pl4, vh);
                mma_bf16(o[2 * u + 1], ph, vh + 2); mma_bf16(o[2 * u + 1], ph, vl + 2);
                mma_bf16(o[2 * u + 1], pl4, vh + 2);
            }
        }

        __syncthreads();
        if (has_next) issue_V(sc0 + 32);
        cp_commit();
        cp_wait1();
        __syncthreads();
    }

    float inv0 = __fdividef(1.f, l2[0]);
    float inv1 = __fdividef(1.f, l2[1]);
    #pragma unroll
    for (int nt = 0; nt < 16; nt++) {
        int dim = wc * 128 + nt * 8 + 2 * t4;
        float v0 = o[nt][0] * inv0, v1 = o[nt][1] * inv0;
        float v2 = o[nt][2] * inv1, v3 = o[nt][3] * inv1;
        __nv_bfloat16 h0, l0, h1, l1, h2, lo2, h3, l3;
        split_bf16(v0, h0, l0); split_bf16(v1, h1, l1);
        split_bf16(v2, h2, lo2); split_bf16(v3, h3, l3);
        size_t adr0 = ((size_t)tq0 * 16 + n) * 256 + dim;
        size_t adr1 = ((size_t)tq1 * 16 + n) * 256 + dim;
        *reinterpret_cast<__nv_bfloat162*>(g_ench + adr0) = __nv_bfloat162(h0, h1);
        *reinterpret_cast<__nv_bfloat162*>(g_encl + adr0) = __nv_bfloat162(l0, l1);
        *reinterpret_cast<__nv_bfloat162*>(g_ench + adr1) = __nv_bfloat162(h2, h3);
        *reinterpret_cast<__nv_bfloat162*>(g_encl + adr1) = __nv_bfloat162(lo2, l3);
    }
}

// ================= launch =================
extern "C" void kernel_launch(void* const* d_in, const int* in_sizes, int n_in,
                              void* d_out, int out_size)
{
    const float* x       = (const float*)d_in[0];
    const int*   segpos  = (const int*)  d_in[1];
    const float* w_q     = (const float*)d_in[3];
    const float* w_kv    = (const float*)d_in[4];
    const float* w_out   = (const float*)d_in[5];
    const float* q_scale = (const float*)d_in[6];
    const float* k_scale = (const float*)d_in[7];
    float*       out     = (float*)d_out;

    __nv_bfloat16 *xh, *xl, *wallh, *walll, *woh, *wol, *ench, *encl;
    float *gqkv;
    cudaGetSymbolAddress((void**)&xh,    g_xh);
    cudaGetSymbolAddress((void**)&xl,    g_xl);
    cudaGetSymbolAddress((void**)&wallh, g_wallh);
    cudaGetSymbolAddress((void**)&walll, g_walll);
    cudaGetSymbolAddress((void**)&woh,   g_woh);
    cudaGetSymbolAddress((void**)&wol,   g_wol);
    cudaGetSymbolAddress((void**)&ench,  g_ench);
    cudaGetSymbolAddress((void**)&encl,  g_encl);
    cudaGetSymbolAddress((void**)&gqkv,  g_qkv);

    const dim3 blk(256);
    const size_t hslot = (size_t)HDIM * D_MODEL;

    // 0. precision prep
    convert_x_kernel<<<(T_SEQ * D_MODEL) / (256 * 4), blk>>>(x);
    transpose_conv_kernel<<<dim3(HDIM / 32, D_MODEL / 32, 16), blk>>>(
        w_q, wallh, walll, D_MODEL, HDIM);
    transpose_conv_kernel<<<dim3(HDIM / 32, D_MODEL / 32, 16), blk>>>(
        w_kv, wallh + 16 * hslot, walll + 16 * hslot, D_MODEL, HDIM);
    transpose_conv_kernel<<<dim3(D_MODEL / 32, (N_HEADS * HDIM) / 32, 1), blk>>>(
        w_out, woh, wol, N_HEADS * HDIM, D_MODEL);

    // 1. merged Q+K+V projection: persistent 2-stage, 2 CTAs/SM, 2048 tiles over 296 workers
    cudaFuncSetAttribute(gemm2_bf16_kernel, cudaFuncAttributeMaxDynamicSharedMemorySize, GEMM2_SMEM);
    gemm2_bf16_kernel<<<296, blk, GEMM2_SMEM>>>(
        xh, xl, wallh, walll, gqkv, D_MODEL, 32 * HDIM,
        (32 * HDIM) / GNT, (T_SEQ / GMT) * ((32 * HDIM) / GNT));

    // 2. fused norms + rope -> bf16 hi/lo planes
    norm_rope_all_kernel<<<(T_SEQ * 32) / 8, blk>>>(q_scale, k_scale, segpos);

    // 3. attention (tensor cores)
    cudaFuncSetAttribute(attn_mma_kernel, cudaFuncAttributeMaxDynamicSharedMemorySize, ATTN_SMEM);
    attn_mma_kernel<<<dim3(T_SEQ / 64, N_HEADS), blk, ATTN_SMEM>>>();

    // 4. output projection: same persistent kernel, 768 tiles over 296 workers
    gemm2_bf16_kernel<<<296, blk, GEMM2_SMEM>>>(
        ench, encl, woh, wol, out, N_HEADS * HDIM, D_MODEL,
        D_MODEL / GNT, (T_SEQ / GMT) * (D_MODEL / GNT));
}

// round 10
// speedup vs baseline: 1.2754x; 1.2754x over previous
#include <cuda_runtime.h>
#include <cuda_bf16.h>
#include <cuda_fp16.h>
#include <math.h>
#include <stdint.h>

// ---------------- problem constants ----------------
#define T_SEQ   2048
#define D_MODEL 3072
#define N_HEADS 16
#define K_HEADS 8
#define HDIM    256
#define WINDOW  1024
#define SOFT_CAP 50.0f
#define EPS 1e-6f

// ---------------- scratch (static device globals) ----------------
__device__ float g_qkv[(size_t)T_SEQ * 32 * HDIM];          // [t][slot][h] q0-15,k16-23,v24-31
__device__ __nv_bfloat16 g_xh [(size_t)T_SEQ * D_MODEL];
__device__ __nv_bfloat16 g_xl [(size_t)T_SEQ * D_MODEL];
__device__ __nv_bfloat16 g_qh [(size_t)T_SEQ * N_HEADS * HDIM];
__device__ __nv_bfloat16 g_ql [(size_t)T_SEQ * N_HEADS * HDIM];
__device__ __nv_bfloat16 g_kvh[(size_t)T_SEQ * 16 * HDIM];
__device__ __nv_bfloat16 g_kvl[(size_t)T_SEQ * 16 * HDIM];
__device__ __nv_bfloat16 g_wallh[(size_t)32 * HDIM * D_MODEL];  // [slot][h][d] K-major
__device__ __nv_bfloat16 g_walll[(size_t)32 * HDIM * D_MODEL];
__device__ __half g_wo16 [(size_t)D_MODEL * N_HEADS * HDIM];    // [d][nh*h] K-major fp16
__device__ __half g_enc16[(size_t)T_SEQ * N_HEADS * HDIM];      // enc fp16

// ---------------- low-level helpers ----------------
__device__ __forceinline__ uint32_t smem_u32(const void* p) {
    uint32_t a;
    asm("{ .reg .u64 t; cvta.to.shared.u64 t, %1; cvt.u32.u64 %0, t; }" : "=r"(a) : "l"(p));
    return a;
}
__device__ __forceinline__ void cp_async16(uint32_t dst, const void* src) {
    asm volatile("cp.async.cg.shared.global [%0], [%1], 16;" :: "r"(dst), "l"(src));
}
__device__ __forceinline__ void cp_commit() { asm volatile("cp.async.commit_group;"); }
__device__ __forceinline__ void cp_wait1()  { asm volatile("cp.async.wait_group 1;"); }

__device__ __forceinline__ void ldsm_x4(uint32_t& r0, uint32_t& r1, uint32_t& r2, uint32_t& r3,
                                        uint32_t addr) {
    asm volatile("ldmatrix.sync.aligned.m8n8.x4.shared.b16 {%0,%1,%2,%3}, [%4];"
                 : "=r"(r0), "=r"(r1), "=r"(r2), "=r"(r3) : "r"(addr));
}
__device__ __forceinline__ void ldsm_x4t(uint32_t& r0, uint32_t& r1, uint32_t& r2, uint32_t& r3,
                                         uint32_t addr) {
    asm volatile("ldmatrix.sync.aligned.m8n8.x4.trans.shared.b16 {%0,%1,%2,%3}, [%4];"
                 : "=r"(r0), "=r"(r1), "=r"(r2), "=r"(r3) : "r"(addr));
}
__device__ __forceinline__ void mma_bf16(float* c, const uint32_t* a, const uint32_t* b) {
    asm volatile("mma.sync.aligned.m16n8k16.row.col.f32.bf16.bf16.f32 "
                 "{%0,%1,%2,%3},{%4,%5,%6,%7},{%8,%9},{%0,%1,%2,%3};"
                 : "+f"(c[0]), "+f"(c[1]), "+f"(c[2]), "+f"(c[3])
                 : "r"(a[0]), "r"(a[1]), "r"(a[2]), "r"(a[3]), "r"(b[0]), "r"(b[1]));
}
__device__ __forceinline__ void mma_fp16(float* c, const uint32_t* a, const uint32_t* b) {
    asm volatile("mma.sync.aligned.m16n8k16.row.col.f32.f16.f16.f32 "
                 "{%0,%1,%2,%3},{%4,%5,%6,%7},{%8,%9},{%0,%1,%2,%3};"
                 : "+f"(c[0]), "+f"(c[1]), "+f"(c[2]), "+f"(c[3])
                 : "r"(a[0]), "r"(a[1]), "r"(a[2]), "r"(a[3]), "r"(b[0]), "r"(b[1]));
}
__device__ __forceinline__ void split_bf16(float x, __nv_bfloat16& h, __nv_bfloat16& l) {
    h = __float2bfloat16(x);
    l = __float2bfloat16(x - __bfloat162float(h));
}

// ================= split-bf16 GEMM for QKV (R8 structure: MT=128, NT=256) =================
#define LDHB 80                       // smem row bytes (40 halves)
#define Q_MT 128
#define Q_NT 256
#define Q_APL (Q_MT * LDHB)           // 10240
#define Q_BPL (Q_NT * LDHB)           // 20480
#define Q_STAGE (2 * Q_APL + 2 * Q_BPL)
#define GEMM_SMEM_QKV (3 * Q_STAGE)   // 184320

__global__ __launch_bounds__(256, 1) void gemm_qkv_kernel(
    const __nv_bfloat16* __restrict__ Ah, const __nv_bfloat16* __restrict__ Al,
    const __nv_bfloat16* __restrict__ Bh, const __nv_bfloat16* __restrict__ Bl,
    float* __restrict__ C, int Kdim, int ldc)
{
    extern __shared__ char smem[];
    const uint32_t sbase = smem_u32(smem);
    const int tid = threadIdx.x;
    const int m0 = blockIdx.x * Q_MT, n0b = blockIdx.y * Q_NT;
    const __nv_bfloat16* Ahm = Ah + (size_t)m0 * Kdim;
    const __nv_bfloat16* Alm = Al + (size_t)m0 * Kdim;
    const __nv_bfloat16* Bhz = Bh + (size_t)n0b * Kdim;
    const __nv_bfloat16* Blz = Bl + (size_t)n0b * Kdim;
    const int NK = Kdim / 32;

    const int wid = tid >> 5, lane = tid & 31;
    const int wm = wid & 1, wn = wid >> 1;     // 2M x 4N, warp 64x64, JW=8
    const int g = lane >> 2, t4 = lane & 3;

    auto issue_stage = [&](int s, int kt) {
        const int k0 = kt * 32;
        const uint32_t stg = sbase + s * Q_STAGE;
        #pragma unroll
        for (int i = 0; i < 2; i++) {
            int idx = tid + i * 256;
            int r = idx >> 2, c = idx & 3;
            size_t goff = (size_t)r * Kdim + k0 + c * 8;
            uint32_t d = stg + r * LDHB + c * 16;
            cp_async16(d,         Ahm + goff);
            cp_async16(d + Q_APL, Alm + goff);
        }
        #pragma unroll
        for (int i = 0; i < 4; i++) {
            int idx = tid + i * 256;
            int r = idx >> 2, c = idx & 3;
            size_t goff = (size_t)r * Kdim + k0 + c * 8;
            uint32_t d = stg + 2 * Q_APL + r * LDHB + c * 16;
            cp_async16(d,         Bhz + goff);
            cp_async16(d + Q_BPL, Blz + goff);
        }
    };

    float acc[4][8][4];
    #pragma unroll
    for (int i = 0; i < 4; i++)
        #pragma unroll
        for (int j = 0; j < 8; j++)
            #pragma unroll
            for (int r = 0; r < 4; r++) acc[i][j][r] = 0.f;

    const int arow = wm * 64 + (lane & 7) + ((lane >> 3) & 1) * 8;
    const int akof = ((lane >> 4) & 1) * 8;
    const int brow = wn * 64 + (lane & 7) + ((lane >> 4) & 1) * 8;
    const int bkof = ((lane >> 3) & 1) * 8;

    issue_stage(0, 0); cp_commit();
    issue_stage(1, 1); cp_commit();

    for (int kt = 0; kt < NK; kt++) {
        cp_wait1();
        __syncthreads();
        if (kt + 2 < NK) issue_stage((kt + 2) % 3, kt + 2);
        cp_commit();

        const uint32_t st = sbase + (kt % 3) * Q_STAGE;
        #pragma unroll
        for (int ks = 0; ks < 2; ks++) {
            uint32_t ah[4][4], al[4][4];
            #pragma unroll
            for (int i = 0; i < 4; i++) {
                uint32_t ad = st + (arow + i * 16) * LDHB + (ks * 16 + akof) * 2;
                ldsm_x4(ah[i][0], ah[i][1], ah[i][2], ah[i][3], ad);
                ldsm_x4(al[i][0], al[i][1], al[i][2], al[i][3], ad + Q_APL);
            }
            #pragma unroll
            for (int jp = 0; jp < 4; jp++) {
                uint32_t bd = st + 2 * Q_APL + (brow + jp * 16) * LDHB + (ks * 16 + bkof) * 2;
                uint32_t bh[4], bl[4];
                ldsm_x4(bh[0], bh[1], bh[2], bh[3], bd);
                ldsm_x4(bl[0], bl[1], bl[2], bl[3], bd + Q_BPL);
                #pragma unroll
                for (int i = 0; i < 4; i++) {
                    #pragma unroll
                    for (int jj = 0; jj < 2; jj++) {
                        const int j = 2 * jp + jj;
                        mma_bf16(acc[i][j], ah[i], bh + 2 * jj);
                        mma_bf16(acc[i][j], ah[i], bl + 2 * jj);
                        mma_bf16(acc[i][j], al[i], bh + 2 * jj);
                    }
                }
            }
        }
    }

    #pragma unroll
    for (int i = 0; i < 4; i++) {
        const int r0 = m0 + wm * 64 + i * 16 + g;
        #pragma unroll
        for (int j = 0; j < 8; j++) {
            const int c0 = n0b + wn * 64 + j * 8 + t4 * 2;
            *reinterpret_cast<float2*>(&C[(size_t)r0 * ldc + c0]) =
                make_float2(acc[i][j][0], acc[i][j][1]);
            *reinterpret_cast<float2*>(&C[(size_t)(r0 + 8) * ldc + c0]) =
                make_float2(acc[i][j][2], acc[i][j][3]);
        }
    }
}

// ================= single-fp16 GEMM for OUT (MT=64, NT=128, 1 MMA/product) =================
#define O_MT 64
#define O_NT 128
#define O_APL (O_MT * LDHB)           // 5120
#define O_BPL (O_NT * LDHB)           // 10240
#define O_STAGE (O_APL + O_BPL)       // 15360
#define GEMM_SMEM_OUT (3 * O_STAGE)   // 46080

__global__ __launch_bounds__(256) void gemm_out_f16_kernel(
    const __half* __restrict__ A, const __half* __restrict__ B,
    float* __restrict__ C, int Kdim, int ldc)
{
    extern __shared__ char smem[];
    const uint32_t sbase = smem_u32(smem);
    const int tid = threadIdx.x;
    const int m0 = blockIdx.x * O_MT, n0b = blockIdx.y * O_NT;
    const __half* Am = A + (size_t)m0 * Kdim;
    const __half* Bz = B + (size_t)n0b * Kdim;
    const int NK = Kdim / 32;

    const int wid = tid >> 5, lane = tid & 31;
    const int wn = wid;                          // 1M x 8N, warp 64x16, JW=2
    const int g = lane >> 2, t4 = lane & 3;

    auto issue_stage = [&](int s, int kt) {
        const int k0 = kt * 32;
        const uint32_t stg = sbase + s * O_STAGE;
        {   // A: 256 chunks, 1/thread
            int r = tid >> 2, c = tid & 3;
            cp_async16(stg + r * LDHB + c * 16, Am + (size_t)r * Kdim + k0 + c * 8);
        }
        #pragma unroll
        for (int i = 0; i < 2; i++) {   // B: 512 chunks
            int idx = tid + i * 256;
            int r = idx >> 2, c = idx & 3;
            cp_async16(stg + O_APL + r * LDHB + c * 16, Bz + (size_t)r * Kdim + k0 + c * 8);
        }
    };

    float acc[4][2][4];
    #pragma unroll
    for (int i = 0; i < 4; i++)
        #pragma unroll
        for (int j = 0; j < 2; j++)
            #pragma unroll
            for (int r = 0; r < 4; r++) acc[i][j][r] = 0.f;

    const int arow = (lane & 7) + ((lane >> 3) & 1) * 8;
    const int akof = ((lane >> 4) & 1) * 8;
    const int brow = wn * 16 + (lane & 7) + ((lane >> 4) & 1) * 8;
    const int bkof = ((lane >> 3) & 1) * 8;

    issue_stage(0, 0); cp_commit();
    issue_stage(1, 1); cp_commit();

    for (int kt = 0; kt < NK; kt++) {
        cp_wait1();
        __syncthreads();
        if (kt + 2 < NK) issue_stage((kt + 2) % 3, kt + 2);
        cp_commit();

        const uint32_t st = sbase + (kt % 3) * O_STAGE;
        #pragma unroll
        for (int ks = 0; ks < 2; ks++) {
            uint32_t ah[4][4];
            #pragma unroll
            for (int i = 0; i < 4; i++) {
                uint32_t ad = st + (arow + i * 16) * LDHB + (ks * 16 + akof) * 2;
                ldsm_x4(ah[i][0], ah[i][1], ah[i][2], ah[i][3], ad);
            }
            uint32_t bd = st + O_APL + brow * LDHB + (ks * 16 + bkof) * 2;
            uint32_t bh[4];
            ldsm_x4(bh[0], bh[1], bh[2], bh[3], bd);
            #pragma unroll
            for (int i = 0; i < 4; i++) {
                mma_fp16(acc[i][0], ah[i], bh);
                mma_fp16(acc[i][1], ah[i], bh + 2);
            }
        }
    }

    #pragma unroll
    for (int i = 0; i < 4; i++) {
        const int r0 = m0 + i * 16 + g;
        #pragma unroll
        for (int j = 0; j < 2; j++) {
            const int c0 = n0b + wn * 16 + j * 8 + t4 * 2;
            *reinterpret_cast<float2*>(&C[(size_t)r0 * ldc + c0]) =
                make_float2(acc[i][j][0], acc[i][j][1]);
            *reinterpret_cast<float2*>(&C[(size_t)(r0 + 8) * ldc + c0]) =
                make_float2(acc[i][j][2], acc[i][j][3]);
        }
    }
}

// ================= x -> bf16 hi/lo planes =================
__global__ __launch_bounds__(256) void convert_x_kernel(const float* __restrict__ x)
{
    size_t i = ((size_t)blockIdx.x * 256 + threadIdx.x) * 4;
    float4 v = *reinterpret_cast<const float4*>(x + i);
    __nv_bfloat16 h[4], l[4];
    split_bf16(v.x, h[0], l[0]); split_bf16(v.y, h[1], l[1]);
    split_bf16(v.z, h[2], l[2]); split_bf16(v.w, h[3], l[3]);
    *reinterpret_cast<__nv_bfloat162*>(g_xh + i)     = __nv_bfloat162(h[0], h[1]);
    *reinterpret_cast<__nv_bfloat162*>(g_xh + i + 2) = __nv_bfloat162(h[2], h[3]);
    *reinterpret_cast<__nv_bfloat162*>(g_xl + i)     = __nv_bfloat162(l[0], l[1]);
    *reinterpret_cast<__nv_bfloat162*>(g_xl + i + 2) = __nv_bfloat162(l[2], l[3]);
}

// ================= transpose + convert (bf16 hi/lo) =================
__global__ __launch_bounds__(256) void transpose_conv_kernel(
    const float* __restrict__ in, __nv_bfloat16* __restrict__ outh,
    __nv_bfloat16* __restrict__ outl, int R, int C)
{
    __shared__ float t[32][33];
    size_t zo = (size_t)blockIdx.z * R * C;
    int c0 = blockIdx.x * 32, r0 = blockIdx.y * 32;
    int tx = threadIdx.x & 31, ty = threadIdx.x >> 5;
    #pragma unroll
    for (int i = 0; i < 32; i += 8)
        t[ty + i][tx] = in[zo + (size_t)(r0 + ty + i) * C + c0 + tx];
    __syncthreads();
    #pragma unroll
    for (int i = 0; i < 32; i += 8) {
        float v = t[tx][ty + i];
        __nv_bfloat16 h, l;
        split_bf16(v, h, l);
        size_t o = zo + (size_t)(c0 + ty + i) * R + r0 + tx;
        outh[o] = h;
        outl[o] = l;
    }
}

// ================= transpose + convert (fp16 single) =================
__global__ __launch_bounds__(256) void transpose_conv_f16_kernel(
    const float* __restrict__ in, __half* __restrict__ outp, int R, int C)
{
    __shared__ float t[32][33];
    int c0 = blockIdx.x * 32, r0 = blockIdx.y * 32;
    int tx = threadIdx.x & 31, ty = threadIdx.x >> 5;
    #pragma unroll
    for (int i = 0; i < 32; i += 8)
        t[ty + i][tx] = in[(size_t)(r0 + ty + i) * C + c0 + tx];
    __syncthreads();
    #pragma unroll
    for (int i = 0; i < 32; i += 8)
        outp[(size_t)(c0 + ty + i) * R + r0 + tx] = __float2half(t[tx][ty + i]);
}

// ================= fused RMS-norm (+scale) (+RoPE) over all 32 slots =================
__device__ __forceinline__ void rope_apply(float v[8], int lane, int pos)
{
    #pragma unroll
    for (int j = 0; j < 4; j++) {
        int hh = lane + 32 * j;
        float ts = powf(10000.0f, (float)hh * (1.0f / 128.0f));
        float arg = (float)pos / ts;
        float sn, cs;
        sincosf(arg, &sn, &cs);
        float f = v[j], s = v[j + 4];
        v[j]     = f * cs - s * sn;
        v[j + 4] = s * cs + f * sn;
    }
}

__global__ __launch_bounds__(256) void norm_rope_all_kernel(const float* __restrict__ qscale,
                                                            const float* __restrict__ kscale,
                                                            const int* __restrict__ segpos)
{
    int row  = blockIdx.x * 8 + (threadIdx.x >> 5);   // 0..T*32-1
    int lane = threadIdx.x & 31;
    int t    = row >> 5;
    int slot = row & 31;                               // 0-15 q, 16-23 k, 24-31 v
    const float* p = g_qkv + (size_t)row * HDIM;

    float v[8]; float ss = 0.f;
    #pragma unroll
    for (int j = 0; j < 8; j++) { v[j] = p[lane + 32 * j]; ss += v[j] * v[j]; }
    #pragma unroll
    for (int o = 16; o > 0; o >>= 1) ss += __shfl_xor_sync(0xffffffffu, ss, o);
    float rstd = rsqrtf(ss * (1.0f / 256.0f) + EPS);

    if (slot < 16) {
        #pragma unroll
        for (int j = 0; j < 8; j++) {
            int h = lane + 32 * j;
            v[j] = v[j] * rstd * (1.0f + qscale[h]);
        }
        rope_apply(v, lane, segpos[t]);
        #pragma unroll
        for (int j = 0; j < 8; j++) {
            int h = lane + 32 * j;
            __nv_bfloat16 hh, ll;
            split_bf16(v[j], hh, ll);
            size_t o = ((size_t)t * 16 + slot) * HDIM + h;
            g_qh[o] = hh; g_ql[o] = ll;
        }
    } else if (slot < 24) {
        #pragma unroll
        for (int j = 0; j < 8; j++) {
            int h = lane + 32 * j;
            v[j] = v[j] * rstd * (1.0f + kscale[h]);
        }
        rope_apply(v, lane, segpos[t]);
        #pragma unroll
        for (int j = 0; j < 8; j++) {
            int h = lane + 32 * j;
            __nv_bfloat16 hh, ll;
            split_bf16(v[j], hh, ll);
            size_t o = ((size_t)t * 16 + (slot - 16)) * HDIM + h;
            g_kvh[o] = hh; g_kvl[o] = ll;
        }
    } else {
        #pragma unroll
        for (int j = 0; j < 8; j++) {
            int h = lane + 32 * j;
            float vv = v[j] * rstd;
            __nv_bfloat16 hh, ll;
            split_bf16(vv, hh, ll);
            size_t o = ((size_t)t * 16 + (slot - 24) + 8) * HDIM + h;
            g_kvh[o] = hh; g_kvl[o] = ll;
        }
    }
}

// ================= tensor-core flash attention (R6 winner; fp16 enc epilogue) =================
#define SROWB 528
#define QPL 33792
#define KPL 16896
#define PROWB 80
#define PPL (64 * PROWB)
#define ATTN_SMEM (2 * QPL + 4 * KPL + 2 * PPL + 1024)

__global__ __launch_bounds__(256, 1) void attn_mma_kernel()
{
    extern __shared__ char smc[];
    const uint32_t sb = smem_u32(smc);
    const int tid = threadIdx.x;
    const int wid = tid >> 5, lane = tid & 31;
    const int t0 = blockIdx.x * 64;
    const int n  = blockIdx.y;
    const int hp = n >> 1;
    const int wr = wid & 3, wc = wid >> 2;
    const int R  = wr * 16;
    const int g = lane >> 2, t4 = lane & 3;

    const uint32_t sQh = sb, sQl = sb + QPL;
    const uint32_t sKh = sb + 2 * QPL;
    const uint32_t sKl = sKh + KPL;
    const uint32_t sVh = sKh + 2 * KPL;
    const uint32_t sVl = sKh + 3 * KPL;
    const uint32_t sPh = sb + 2 * QPL + 4 * KPL;
    const uint32_t sPl = sPh + PPL;
    float* redmax = reinterpret_cast<float*>(smc + 2 * QPL + 4 * KPL + 2 * PPL);
    float* redsum = redmax + 128;

    #pragma unroll
    for (int i = 0; i < 16; i++) {
        int idx = tid + i * 256;
        int pl = idx >> 11;
        int r = (idx >> 5) & 63, c = idx & 31;
        const __nv_bfloat16* src = (pl ? g_ql : g_qh) +
            ((size_t)(t0 + r) * 16 + n) * 256 + c * 8;
        cp_async16(sb + pl * QPL + r * SROWB + c * 16, src);
    }
    cp_commit();

    auto issue_K = [&](int sc0) {
        #pragma unroll
        for (int i = 0; i < 8; i++) {
            int idx = tid + i * 256;
            int pl = idx >> 10;
            int r = (idx >> 5) & 31, c = idx & 31;
            const __nv_bfloat16* src = (pl ? g_kvl : g_kvh) +
                ((size_t)(sc0 + r) * 16 + hp) * 256 + c * 8;
            cp_async16(sKh + pl * KPL + r * SROWB + c * 16, src);
        }
    };
    auto issue_V = [&](int sc0) {
        #pragma unroll
        for (int i = 0; i < 8; i++) {
            int idx = tid + i * 256;
            int pl = idx >> 10;
            int r = (idx >> 5) & 31, c = idx & 31;
            const __nv_bfloat16* src = (pl ? g_kvl : g_kvh) +
                ((size_t)(sc0 + r) * 16 + 8 + hp) * 256 + c * 8;
            cp_async16(sVh + pl * KPL + r * SROWB + c * 16, src);
        }
    };

    float o[16][4];
    #pragma unroll
    for (int i = 0; i < 16; i++)
        #pragma unroll
        for (int c = 0; c < 4; c++) o[i][c] = 0.f;
    float m2[2] = {-1e29f, -1e29f}, l2[2] = {0.f, 0.f};

    int s_lo = t0 - (WINDOW - 1); if (s_lo < 0) s_lo = 0; s_lo &= ~31;

    const int aoff  = (R + (lane & 7) + ((lane >> 3) & 1) * 8) * SROWB + ((lane >> 4) & 1) * 16;
    const int koff  = (((lane >> 4) & 1) * 8 + (lane & 7)) * SROWB + ((lane >> 3) & 1) * 16
                      + wc * 16 * SROWB;
    const int voff  = (((lane >> 3) & 1) * 8 + (lane & 7)) * SROWB + ((lane >> 4) & 1) * 16
                      + wc * 256;
    const int aoffP = (R + (lane & 7) + ((lane >> 3) & 1) * 8) * PROWB + ((lane >> 4) & 1) * 16;
    const int tq0 = t0 + R + g, tq1 = tq0 + 8;

    issue_K(s_lo); cp_commit();
    issue_V(s_lo); cp_commit();
    asm volatile("cp.async.wait_group 1;");
    __syncthreads();

    for (int sc0 = s_lo; sc0 <= t0 + 63; sc0 += 32) {
        const bool has_next = (sc0 + 32 <= t0 + 63);

        float s[2][4];
        #pragma unroll
        for (int j = 0; j < 2; j++)
            #pragma unroll
            for (int c = 0; c < 4; c++) s[j][c] = 0.f;

        #pragma unroll 4
        for (int hs = 0; hs < 16; hs++) {
            uint32_t qh[4], ql[4], kh[4], kl[4];
            ldsm_x4(qh[0], qh[1], qh[2], qh[3], sQh + aoff + hs * 32);
            ldsm_x4(ql[0], ql[1], ql[2], ql[3], sQl + aoff + hs * 32);
            ldsm_x4(kh[0], kh[1], kh[2], kh[3], sKh + koff + hs * 32);
            ldsm_x4(kl[0], kl[1], kl[2], kl[3], sKl + koff + hs * 32);
            mma_bf16(s[0], qh, kh); mma_bf16(s[0], qh, kl); mma_bf16(s[0], ql, kh);
            mma_bf16(s[1], qh, kh + 2); mma_bf16(s[1], qh, kl + 2); mma_bf16(s[1], ql, kh + 2);
        }

        #pragma unroll
        for (int j = 0; j < 2; j++)
            #pragma unroll
            for (int c = 0; c < 4; c++) {
                int tq = (c >> 1) ? tq1 : tq0;
                int sk = sc0 + wc * 16 + j * 8 + 2 * t4 + (c & 1);
                float xx = s[j][c] * (1.0f / SOFT_CAP);
                xx = fminf(fmaxf(xx, -10.f), 10.f);
                float e = __expf(2.0f * xx);
                float val = SOFT_CAP * __fdividef(e - 1.0f, e + 1.0f);
                bool ok = (sk <= tq) && (sk > tq - WINDOW);
                s[j][c] = ok ? val : -1e30f;
            }

        float mx0 = fmaxf(fmaxf(s[0][0], s[0][1]), fmaxf(s[1][0], s[1][1]));
        float mx1 = fmaxf(fmaxf(s[0][2], s[0][3]), fmaxf(s[1][2], s[1][3]));
        mx0 = fmaxf(mx0, __shfl_xor_sync(0xffffffffu, mx0, 1));
        mx0 = fmaxf(mx0, __shfl_xor_sync(0xffffffffu, mx0, 2));
        mx1 = fmaxf(mx1, __shfl_xor_sync(0xffffffffu, mx1, 1));
        mx1 = fmaxf(mx1, __shfl_xor_sync(0xffffffffu, mx1, 2));
        if (t4 == 0) {
            redmax[wc * 64 + R + g] = mx0;
            redmax[wc * 64 + R + g + 8] = mx1;
        }
        __syncthreads();

        if (has_next) issue_K(sc0 + 32);
        cp_commit();

        float cm0 = fmaxf(mx0, redmax[(1 - wc) * 64 + R + g]);
        float cm1 = fmaxf(mx1, redmax[(1 - wc) * 64 + R + g + 8]);
        float mn0 = fmaxf(m2[0], cm0), mn1 = fmaxf(m2[1], cm1);
        float a0 = __expf(m2[0] - mn0), a1 = __expf(m2[1] - mn1);
        m2[0] = mn0; m2[1] = mn1;

        float sum0 = 0.f, sum1 = 0.f;
        #pragma unroll
        for (int j = 0; j < 2; j++) {
            s[j][0] = __expf(s[j][0] - mn0); sum0 += s[j][0];
            s[j][1] = __expf(s[j][1] - mn0); sum0 += s[j][1];
            s[j][2] = __expf(s[j][2] - mn1); sum1 += s[j][2];
            s[j][3] = __expf(s[j][3] - mn1); sum1 += s[j][3];
        }
        sum0 += __shfl_xor_sync(0xffffffffu, sum0, 1);
        sum0 += __shfl_xor_sync(0xffffffffu, sum0, 2);
        sum1 += __shfl_xor_sync(0xffffffffu, sum1, 1);
        sum1 += __shfl_xor_sync(0xffffffffu, sum1, 2);
        if (t4 == 0) {
            redsum[wc * 64 + R + g] = sum0;
            redsum[wc * 64 + R + g + 8] = sum1;
        }

        #pragma unroll
        for (int j = 0; j < 2; j++) {
            int kcol = wc * 16 + j * 8 + 2 * t4;
            __nv_bfloat16 h0, l0, h1, l1;
            split_bf16(s[j][0], h0, l0); split_bf16(s[j][1], h1, l1);
            *reinterpret_cast<__nv_bfloat162*>(smc + (sPh - sb) + (R + g) * PROWB + kcol * 2) =
                __nv_bfloat162(h0, h1);
            *reinterpret_cast<__nv_bfloat162*>(smc + (sPl - sb) + (R + g) * PROWB + kcol * 2) =
                __nv_bfloat162(l0, l1);
            split_bf16(s[j][2], h0, l0); split_bf16(s[j][3], h1, l1);
            *reinterpret_cast<__nv_bfloat162*>(smc + (sPh - sb) + (R + g + 8) * PROWB + kcol * 2) =
                __nv_bfloat162(h0, h1);
            *reinterpret_cast<__nv_bfloat162*>(smc + (sPl - sb) + (R + g + 8) * PROWB + kcol * 2) =
                __nv_bfloat162(l0, l1);
        }

        cp_wait1();
        __syncthreads();

        l2[0] = l2[0] * a0 + sum0 + redsum[(1 - wc) * 64 + R + g];
        l2[1] = l2[1] * a1 + sum1 + redsum[(1 - wc) * 64 + R + g + 8];

        if (a0 != 1.f || a1 != 1.f) {
            #pragma unroll
            for (int i = 0; i < 16; i++) {
                o[i][0] *= a0; o[i][1] *= a0;
                o[i][2] *= a1; o[i][3] *= a1;
            }
        }

        #pragma unroll
        for (int ks = 0; ks < 2; ks++) {
            uint32_t ph[4], pl4[4];
            ldsm_x4(ph[0], ph[1], ph[2], ph[3], sPh + aoffP + ks * 32);
            ldsm_x4(pl4[0], pl4[1], pl4[2], pl4[3], sPl + aoffP + ks * 32);
            #pragma unroll
            for (int u = 0; u < 8; u++) {
                uint32_t vh[4], vl[4];
                uint32_t va = sVh + voff + ks * 16 * SROWB + u * 32;
                ldsm_x4t(vh[0], vh[1], vh[2], vh[3], va);
                ldsm_x4t(vl[0], vl[1], vl[2], vl[3], va + KPL);
                mma_bf16(o[2 * u], ph, vh);     mma_bf16(o[2 * u], ph, vl);
                mma_bf16(o[2 * u], pl4, vh);
                mma_bf16(o[2 * u + 1], ph, vh + 2); mma_bf16(o[2 * u + 1], ph, vl + 2);
                mma_bf16(o[2 * u + 1], pl4, vh + 2);
            }
        }

        __syncthreads();
        if (has_next) issue_V(sc0 + 32);
        cp_commit();
        cp_wait1();
        __syncthreads();
    }

    // epilogue: normalize, write enc as fp16
    float inv0 = __fdividef(1.f, l2[0]);
    float inv1 = __fdividef(1.f, l2[1]);
    #pragma unroll
    for (int nt = 0; nt < 16; nt++) {
        int dim = wc * 128 + nt * 8 + 2 * t4;
        float v0 = o[nt][0] * inv0, v1 = o[nt][1] * inv0;
        float v2 = o[nt][2] * inv1, v3 = o[nt][3] * inv1;
        size_t adr0 = ((size_t)tq0 * 16 + n) * 256 + dim;
        size_t adr1 = ((size_t)tq1 * 16 + n) * 256 + dim;
        *reinterpret_cast<__half2*>(g_enc16 + adr0) = __floats2half2_rn(v0, v1);
        *reinterpret_cast<__half2*>(g_enc16 + adr1) = __floats2half2_rn(v2, v3);
    }
}

// ================= launch =================
extern "C" void kernel_launch(void* const* d_in, const int* in_sizes, int n_in,
                              void* d_out, int out_size)
{
    const float* x       = (const float*)d_in[0];
    const int*   segpos  = (const int*)  d_in[1];
    const float* w_q     = (const float*)d_in[3];
    const float* w_kv    = (const float*)d_in[4];
    const float* w_out   = (const float*)d_in[5];
    const float* q_scale = (const float*)d_in[6];
    const float* k_scale = (const float*)d_in[7];
    float*       out     = (float*)d_out;

    __nv_bfloat16 *xh, *xl, *wallh, *walll;
    __half *wo16, *enc16;
    float *gqkv;
    cudaGetSymbolAddress((void**)&xh,    g_xh);
    cudaGetSymbolAddress((void**)&xl,    g_xl);
    cudaGetSymbolAddress((void**)&wallh, g_wallh);
    cudaGetSymbolAddress((void**)&walll, g_walll);
    cudaGetSymbolAddress((void**)&wo16,  g_wo16);
    cudaGetSymbolAddress((void**)&enc16, g_enc16);
    cudaGetSymbolAddress((void**)&gqkv,  g_qkv);

    const dim3 blk(256);
    const size_t hslot = (size_t)HDIM * D_MODEL;

    // 0. precision prep
    convert_x_kernel<<<(T_SEQ * D_MODEL) / (256 * 4), blk>>>(x);
    transpose_conv_kernel<<<dim3(HDIM / 32, D_MODEL / 32, 16), blk>>>(
        w_q, wallh, walll, D_MODEL, HDIM);
    transpose_conv_kernel<<<dim3(HDIM / 32, D_MODEL / 32, 16), blk>>>(
        w_kv, wallh + 16 * hslot, walll + 16 * hslot, D_MODEL, HDIM);
    transpose_conv_f16_kernel<<<dim3(D_MODEL / 32, (N_HEADS * HDIM) / 32), blk>>>(
        w_out, wo16, N_HEADS * HDIM, D_MODEL);

    // 1. merged Q+K+V projection (split-bf16, CTA 128x256)
    cudaFuncSetAttribute(gemm_qkv_kernel, cudaFuncAttributeMaxDynamicSharedMemorySize, GEMM_SMEM_QKV);
    gemm_qkv_kernel<<<dim3(T_SEQ / Q_MT, (32 * HDIM) / Q_NT), blk, GEMM_SMEM_QKV>>>(
        xh, xl, wallh, walll, gqkv, D_MODEL, 32 * HDIM);

    // 2. fused norms + rope -> bf16 hi/lo planes
    norm_rope_all_kernel<<<(T_SEQ * 32) / 8, blk>>>(q_scale, k_scale, segpos);

    // 3. attention (tensor cores) -> enc fp16
    cudaFuncSetAttribute(attn_mma_kernel, cudaFuncAttributeMaxDynamicSharedMemorySize, ATTN_SMEM);
    attn_mma_kernel<<<dim3(T_SEQ / 64, N_HEADS), blk, ATTN_SMEM>>>();

    // 4. output projection (single-fp16, 1 MMA/product)
    cudaFuncSetAttribute(gemm_out_f16_kernel, cudaFuncAttributeMaxDynamicSharedMemorySize, GEMM_SMEM_OUT);
    gemm_out_f16_kernel<<<dim3(T_SEQ / O_MT, D_MODEL / O_NT), blk, GEMM_SMEM_OUT>>>(
        enc16, wo16, out, N_HEADS * HDIM, D_MODEL);
}

// round 12
// speedup vs baseline: 1.4614x; 1.1458x over previous
#include <cuda_runtime.h>
#include <cuda_bf16.h>
#include <cuda_fp16.h>
#include <math.h>
#include <stdint.h>

// ---------------- problem constants ----------------
#define T_SEQ   2048
#define D_MODEL 3072
#define N_HEADS 16
#define K_HEADS 8
#define HDIM    256
#define WINDOW  1024
#define SOFT_CAP 50.0f
#define EPS 1e-6f

// ---------------- scratch (static device globals) ----------------
__device__ float g_qkv[(size_t)T_SEQ * 32 * HDIM];          // [t][slot][h] q0-15,k16-23,v24-31
__device__ __nv_bfloat16 g_xh [(size_t)T_SEQ * D_MODEL];
__device__ __nv_bfloat16 g_xl [(size_t)T_SEQ * D_MODEL];
__device__ __half        g_x16[(size_t)T_SEQ * D_MODEL];
__device__ __nv_bfloat16 g_qh [(size_t)T_SEQ * N_HEADS * HDIM];
__device__ __nv_bfloat16 g_ql [(size_t)T_SEQ * N_HEADS * HDIM];
__device__ __nv_bfloat16 g_kvh[(size_t)T_SEQ * 16 * HDIM];  // K slots 0..7 used
__device__ __nv_bfloat16 g_kvl[(size_t)T_SEQ * 16 * HDIM];
__device__ __half        g_v16[(size_t)T_SEQ * 8 * HDIM];   // V fp16
__device__ __nv_bfloat16 g_wallh[(size_t)32 * HDIM * D_MODEL];  // q+k slots (24 used)
__device__ __nv_bfloat16 g_walll[(size_t)32 * HDIM * D_MODEL];
__device__ __half g_wv16 [(size_t)8 * HDIM * D_MODEL];      // V weights fp16 K-major
__device__ __half g_wo16 [(size_t)D_MODEL * N_HEADS * HDIM];
__device__ __half g_enc16[(size_t)T_SEQ * N_HEADS * HDIM];

// ---------------- low-level helpers ----------------
__device__ __forceinline__ uint32_t smem_u32(const void* p) {
    uint32_t a;
    asm("{ .reg .u64 t; cvta.to.shared.u64 t, %1; cvt.u32.u64 %0, t; }" : "=r"(a) : "l"(p));
    return a;
}
__device__ __forceinline__ void cp_async16(uint32_t dst, const void* src) {
    asm volatile("cp.async.cg.shared.global [%0], [%1], 16;" :: "r"(dst), "l"(src));
}
__device__ __forceinline__ void cp_commit() { asm volatile("cp.async.commit_group;"); }
__device__ __forceinline__ void cp_wait1()  { asm volatile("cp.async.wait_group 1;"); }

__device__ __forceinline__ void ldsm_x4(uint32_t& r0, uint32_t& r1, uint32_t& r2, uint32_t& r3,
                                        uint32_t addr) {
    asm volatile("ldmatrix.sync.aligned.m8n8.x4.shared.b16 {%0,%1,%2,%3}, [%4];"
                 : "=r"(r0), "=r"(r1), "=r"(r2), "=r"(r3) : "r"(addr));
}
__device__ __forceinline__ void ldsm_x4t(uint32_t& r0, uint32_t& r1, uint32_t& r2, uint32_t& r3,
                                         uint32_t addr) {
    asm volatile("ldmatrix.sync.aligned.m8n8.x4.trans.shared.b16 {%0,%1,%2,%3}, [%4];"
                 : "=r"(r0), "=r"(r1), "=r"(r2), "=r"(r3) : "r"(addr));
}
__device__ __forceinline__ void mma_bf16(float* c, const uint32_t* a, const uint32_t* b) {
    asm volatile("mma.sync.aligned.m16n8k16.row.col.f32.bf16.bf16.f32 "
                 "{%0,%1,%2,%3},{%4,%5,%6,%7},{%8,%9},{%0,%1,%2,%3};"
                 : "+f"(c[0]), "+f"(c[1]), "+f"(c[2]), "+f"(c[3])
                 : "r"(a[0]), "r"(a[1]), "r"(a[2]), "r"(a[3]), "r"(b[0]), "r"(b[1]));
}
__device__ __forceinline__ void mma_fp16(float* c, const uint32_t* a, const uint32_t* b) {
    asm volatile("mma.sync.aligned.m16n8k16.row.col.f32.f16.f16.f32 "
                 "{%0,%1,%2,%3},{%4,%5,%6,%7},{%8,%9},{%0,%1,%2,%3};"
                 : "+f"(c[0]), "+f"(c[1]), "+f"(c[2]), "+f"(c[3])
                 : "r"(a[0]), "r"(a[1]), "r"(a[2]), "r"(a[3]), "r"(b[0]), "r"(b[1]));
}
__device__ __forceinline__ void split_bf16(float x, __nv_bfloat16& h, __nv_bfloat16& l) {
    h = __float2bfloat16(x);
    l = __float2bfloat16(x - __bfloat162float(h));
}

// ================= split-bf16 GEMM for Q+K (MT=128, NT=256) =================
#define LDHB 80
#define Q_MT 128
#define Q_NT 256
#define Q_APL (Q_MT * LDHB)
#define Q_BPL (Q_NT * LDHB)
#define Q_STAGE (2 * Q_APL + 2 * Q_BPL)
#define GEMM_SMEM_QKV (3 * Q_STAGE)   // 184320

__global__ __launch_bounds__(256, 1) void gemm_qkv_kernel(
    const __nv_bfloat16* __restrict__ Ah, const __nv_bfloat16* __restrict__ Al,
    const __nv_bfloat16* __restrict__ Bh, const __nv_bfloat16* __restrict__ Bl,
    float* __restrict__ C, int Kdim, int ldc)
{
    extern __shared__ char smem[];
    const uint32_t sbase = smem_u32(smem);
    const int tid = threadIdx.x;
    const int m0 = blockIdx.x * Q_MT, n0b = blockIdx.y * Q_NT;
    const __nv_bfloat16* Ahm = Ah + (size_t)m0 * Kdim;
    const __nv_bfloat16* Alm = Al + (size_t)m0 * Kdim;
    const __nv_bfloat16* Bhz = Bh + (size_t)n0b * Kdim;
    const __nv_bfloat16* Blz = Bl + (size_t)n0b * Kdim;
    const int NK = Kdim / 32;

    const int wid = tid >> 5, lane = tid & 31;
    const int wm = wid & 1, wn = wid >> 1;     // 2M x 4N, warp 64x64, JW=8
    const int g = lane >> 2, t4 = lane & 3;

    auto issue_stage = [&](int s, int kt) {
        const int k0 = kt * 32;
        const uint32_t stg = sbase + s * Q_STAGE;
        #pragma unroll
        for (int i = 0; i < 2; i++) {
            int idx = tid + i * 256;
            int r = idx >> 2, c = idx & 3;
            size_t goff = (size_t)r * Kdim + k0 + c * 8;
            uint32_t d = stg + r * LDHB + c * 16;
            cp_async16(d,         Ahm + goff);
            cp_async16(d + Q_APL, Alm + goff);
        }
        #pragma unroll
        for (int i = 0; i < 4; i++) {
            int idx = tid + i * 256;
            int r = idx >> 2, c = idx & 3;
            size_t goff = (size_t)r * Kdim + k0 + c * 8;
            uint32_t d = stg + 2 * Q_APL + r * LDHB + c * 16;
            cp_async16(d,         Bhz + goff);
            cp_async16(d + Q_BPL, Blz + goff);
        }
    };

    float acc[4][8][4];
    #pragma unroll
    for (int i = 0; i < 4; i++)
        #pragma unroll
        for (int j = 0; j < 8; j++)
            #pragma unroll
            for (int r = 0; r < 4; r++) acc[i][j][r] = 0.f;

    const int arow = wm * 64 + (lane & 7) + ((lane >> 3) & 1) * 8;
    const int akof = ((lane >> 4) & 1) * 8;
    const int brow = wn * 64 + (lane & 7) + ((lane >> 4) & 1) * 8;
    const int bkof = ((lane >> 3) & 1) * 8;

    issue_stage(0, 0); cp_commit();
    issue_stage(1, 1); cp_commit();

    for (int kt = 0; kt < NK; kt++) {
        cp_wait1();
        __syncthreads();
        if (kt + 2 < NK) issue_stage((kt + 2) % 3, kt + 2);
        cp_commit();

        const uint32_t st = sbase + (kt % 3) * Q_STAGE;
        #pragma unroll
        for (int ks = 0; ks < 2; ks++) {
            uint32_t ah[4][4], al[4][4];
            #pragma unroll
            for (int i = 0; i < 4; i++) {
                uint32_t ad = st + (arow + i * 16) * LDHB + (ks * 16 + akof) * 2;
                ldsm_x4(ah[i][0], ah[i][1], ah[i][2], ah[i][3], ad);
                ldsm_x4(al[i][0], al[i][1], al[i][2], al[i][3], ad + Q_APL);
            }
            #pragma unroll
            for (int jp = 0; jp < 4; jp++) {
                uint32_t bd = st + 2 * Q_APL + (brow + jp * 16) * LDHB + (ks * 16 + bkof) * 2;
                uint32_t bh[4], bl[4];
                ldsm_x4(bh[0], bh[1], bh[2], bh[3], bd);
                ldsm_x4(bl[0], bl[1], bl[2], bl[3], bd + Q_BPL);
                #pragma unroll
                for (int i = 0; i < 4; i++) {
                    #pragma unroll
                    for (int jj = 0; jj < 2; jj++) {
                        const int j = 2 * jp + jj;
                        mma_bf16(acc[i][j], ah[i], bh + 2 * jj);
                        mma_bf16(acc[i][j], ah[i], bl + 2 * jj);
                        mma_bf16(acc[i][j], al[i], bh + 2 * jj);
                    }
                }
            }
        }
    }

    #pragma unroll
    for (int i = 0; i < 4; i++) {
        const int r0 = m0 + wm * 64 + i * 16 + g;
        #pragma unroll
        for (int j = 0; j < 8; j++) {
            const int c0 = n0b + wn * 64 + j * 8 + t4 * 2;
            *reinterpret_cast<float2*>(&C[(size_t)r0 * ldc + c0]) =
                make_float2(acc[i][j][0], acc[i][j][1]);
            *reinterpret_cast<float2*>(&C[(size_t)(r0 + 8) * ldc + c0]) =
                make_float2(acc[i][j][2], acc[i][j][3]);
        }
    }
}

// ================= single-fp16 GEMM (V projection + OUT) =================
#define O_MT 64
#define O_NT 128
#define O_APL (O_MT * LDHB)
#define O_BPL (O_NT * LDHB)
#define O_STAGE (O_APL + O_BPL)
#define GEMM_SMEM_OUT (3 * O_STAGE)   // 46080

__global__ __launch_bounds__(256) void gemm_f16_kernel(
    const __half* __restrict__ A, const __half* __restrict__ B,
    float* __restrict__ C, int Kdim, int ldc, int ccol0)
{
    extern __shared__ char smem[];
    const uint32_t sbase = smem_u32(smem);
    const int tid = threadIdx.x;
    const int m0 = blockIdx.x * O_MT, n0b = blockIdx.y * O_NT;
    const __half* Am = A + (size_t)m0 * Kdim;
    const __half* Bz = B + (size_t)n0b * Kdim;
    const int NK = Kdim / 32;

    const int wid = tid >> 5, lane = tid & 31;
    const int wn = wid;
    const int g = lane >> 2, t4 = lane & 3;

    auto issue_stage = [&](int s, int kt) {
        const int k0 = kt * 32;
        const uint32_t stg = sbase + s * O_STAGE;
        {
            int r = tid >> 2, c = tid & 3;
            cp_async16(stg + r * LDHB + c * 16, Am + (size_t)r * Kdim + k0 + c * 8);
        }
        #pragma unroll
        for (int i = 0; i < 2; i++) {
            int idx = tid + i * 256;
            int r = idx >> 2, c = idx & 3;
            cp_async16(stg + O_APL + r * LDHB + c * 16, Bz + (size_t)r * Kdim + k0 + c * 8);
        }
    };

    float acc[4][2][4];
    #pragma unroll
    for (int i = 0; i < 4; i++)
        #pragma unroll
        for (int j = 0; j < 2; j++)
            #pragma unroll
            for (int r = 0; r < 4; r++) acc[i][j][r] = 0.f;

    const int arow = (lane & 7) + ((lane >> 3) & 1) * 8;
    const int akof = ((lane >> 4) & 1) * 8;
    const int brow = wn * 16 + (lane & 7) + ((lane >> 4) & 1) * 8;
    const int bkof = ((lane >> 3) & 1) * 8;

    issue_stage(0, 0); cp_commit();
    issue_stage(1, 1); cp_commit();

    for (int kt = 0; kt < NK; kt++) {
        cp_wait1();
        __syncthreads();
        if (kt + 2 < NK) issue_stage((kt + 2) % 3, kt + 2);
        cp_commit();

        const uint32_t st = sbase + (kt % 3) * O_STAGE;
        #pragma unroll
        for (int ks = 0; ks < 2; ks++) {
            uint32_t ah[4][4];
            #pragma unroll
            for (int i = 0; i < 4; i++) {
                uint32_t ad = st + (arow + i * 16) * LDHB + (ks * 16 + akof) * 2;
                ldsm_x4(ah[i][0], ah[i][1], ah[i][2], ah[i][3], ad);
            }
            uint32_t bd = st + O_APL + brow * LDHB + (ks * 16 + bkof) * 2;
            uint32_t bh[4];
            ldsm_x4(bh[0], bh[1], bh[2], bh[3], bd);
            #pragma unroll
            for (int i = 0; i < 4; i++) {
                mma_fp16(acc[i][0], ah[i], bh);
                mma_fp16(acc[i][1], ah[i], bh + 2);
            }
        }
    }

    #pragma unroll
    for (int i = 0; i < 4; i++) {
        const int r0 = m0 + i * 16 + g;
        #pragma unroll
        for (int j = 0; j < 2; j++) {
            const int c0 = ccol0 + n0b + wn * 16 + j * 8 + t4 * 2;
            *reinterpret_cast<float2*>(&C[(size_t)r0 * ldc + c0]) =
                make_float2(acc[i][j][0], acc[i][j][1]);
            *reinterpret_cast<float2*>(&C[(size_t)(r0 + 8) * ldc + c0]) =
                make_float2(acc[i][j][2], acc[i][j][3]);
        }
    }
}

// ================= x -> bf16 hi/lo + fp16 planes =================
__global__ __launch_bounds__(256) void convert_x_kernel(const float* __restrict__ x)
{
    size_t i = ((size_t)blockIdx.x * 256 + threadIdx.x) * 4;
    float4 v = *reinterpret_cast<const float4*>(x + i);
    __nv_bfloat16 h[4], l[4];
    split_bf16(v.x, h[0], l[0]); split_bf16(v.y, h[1], l[1]);
    split_bf16(v.z, h[2], l[2]); split_bf16(v.w, h[3], l[3]);
    *reinterpret_cast<__nv_bfloat162*>(g_xh + i)     = __nv_bfloat162(h[0], h[1]);
    *reinterpret_cast<__nv_bfloat162*>(g_xh + i + 2) = __nv_bfloat162(h[2], h[3]);
    *reinterpret_cast<__nv_bfloat162*>(g_xl + i)     = __nv_bfloat162(l[0], l[1]);
    *reinterpret_cast<__nv_bfloat162*>(g_xl + i + 2) = __nv_bfloat162(l[2], l[3]);
    *reinterpret_cast<__half2*>(g_x16 + i)     = __floats2half2_rn(v.x, v.y);
    *reinterpret_cast<__half2*>(g_x16 + i + 2) = __floats2half2_rn(v.z, v.w);
}

// ================= transpose + convert (bf16 hi/lo) =================
__global__ __launch_bounds__(256) void transpose_conv_kernel(
    const float* __restrict__ in, __nv_bfloat16* __restrict__ outh,
    __nv_bfloat16* __restrict__ outl, int R, int C)
{
    __shared__ float t[32][33];
    size_t zo = (size_t)blockIdx.z * R * C;
    int c0 = blockIdx.x * 32, r0 = blockIdx.y * 32;
    int tx = threadIdx.x & 31, ty = threadIdx.x >> 5;
    #pragma unroll
    for (int i = 0; i < 32; i += 8)
        t[ty + i][tx] = in[zo + (size_t)(r0 + ty + i) * C + c0 + tx];
    __syncthreads();
    #pragma unroll
    for (int i = 0; i < 32; i += 8) {
        float v = t[tx][ty + i];
        __nv_bfloat16 h, l;
        split_bf16(v, h, l);
        size_t o = zo + (size_t)(c0 + ty + i) * R + r0 + tx;
        outh[o] = h;
        outl[o] = l;
    }
}

// ================= transpose + convert (fp16 single, z-batched) =================
__global__ __launch_bounds__(256) void transpose_conv_f16_kernel(
    const float* __restrict__ in, __half* __restrict__ outp, int R, int C)
{
    __shared__ float t[32][33];
    size_t zo = (size_t)blockIdx.z * R * C;
    int c0 = blockIdx.x * 32, r0 = blockIdx.y * 32;
    int tx = threadIdx.x & 31, ty = threadIdx.x >> 5;
    #pragma unroll
    for (int i = 0; i < 32; i += 8)
        t[ty + i][tx] = in[zo + (size_t)(r0 + ty + i) * C + c0 + tx];
    __syncthreads();
    #pragma unroll
    for (int i = 0; i < 32; i += 8)
        outp[zo + (size_t)(c0 + ty + i) * R + r0 + tx] = __float2half(t[tx][ty + i]);
}

// ================= fused RMS-norm (+scale) (+RoPE) =================
__device__ __forceinline__ void rope_apply(float v[8], int lane, int pos)
{
    #pragma unroll
    for (int j = 0; j < 4; j++) {
        int hh = lane + 32 * j;
        float ts = powf(10000.0f, (float)hh * (1.0f / 128.0f));
        float arg = (float)pos / ts;
        float sn, cs;
        sincosf(arg, &sn, &cs);
        float f = v[j], s = v[j + 4];
        v[j]     = f * cs - s * sn;
        v[j + 4] = s * cs + f * sn;
    }
}

__global__ __launch_bounds__(256) void norm_rope_all_kernel(const float* __restrict__ qscale,
                                                            const float* __restrict__ kscale,
                                                            const int* __restrict__ segpos)
{
    int row  = blockIdx.x * 8 + (threadIdx.x >> 5);   // 0..T*32-1
    int lane = threadIdx.x & 31;
    int t    = row >> 5;
    int slot = row & 31;                               // 0-15 q, 16-23 k, 24-31 v
    const float* p = g_qkv + (size_t)row * HDIM;

    float v[8]; float ss = 0.f;
    #pragma unroll
    for (int j = 0; j < 8; j++) { v[j] = p[lane + 32 * j]; ss += v[j] * v[j]; }
    #pragma unroll
    for (int o = 16; o > 0; o >>= 1) ss += __shfl_xor_sync(0xffffffffu, ss, o);
    float rstd = rsqrtf(ss * (1.0f / 256.0f) + EPS);

    if (slot < 16) {
        #pragma unroll
        for (int j = 0; j < 8; j++) {
            int h = lane + 32 * j;
            v[j] = v[j] * rstd * (1.0f + qscale[h]);
        }
        rope_apply(v, lane, segpos[t]);
        #pragma unroll
        for (int j = 0; j < 8; j++) {
            int h = lane + 32 * j;
            __nv_bfloat16 hh, ll;
            split_bf16(v[j], hh, ll);
            size_t o = ((size_t)t * 16 + slot) * HDIM + h;
            g_qh[o] = hh; g_ql[o] = ll;
        }
    } else if (slot < 24) {
        #pragma unroll
        for (int j = 0; j < 8; j++) {
            int h = lane + 32 * j;
            v[j] = v[j] * rstd * (1.0f + kscale[h]);
        }
        rope_apply(v, lane, segpos[t]);
        #pragma unroll
        for (int j = 0; j < 8; j++) {
            int h = lane + 32 * j;
            __nv_bfloat16 hh, ll;
            split_bf16(v[j], hh, ll);
            size_t o = ((size_t)t * 16 + (slot - 16)) * HDIM + h;
            g_kvh[o] = hh; g_kvl[o] = ll;
        }
    } else {
        #pragma unroll
        for (int j = 0; j < 8; j++) {
            int h = lane + 32 * j;
            g_v16[((size_t)t * 8 + (slot - 24)) * HDIM + h] = __float2half(v[j] * rstd);
        }
    }
}

// ================= tensor-core flash attention (QK 3-term, PV fp16 single) =================
#define SROWB 528
#define QPL 33792
#define KPL 16896
#define PROWB 80
#define PPL (64 * PROWB)
#define ATTN_SMEM (2 * QPL + 3 * KPL + PPL + 1024)   // 124416

__global__ __launch_bounds__(256, 1) void attn_mma_kernel()
{
    extern __shared__ char smc[];
    const uint32_t sb = smem_u32(smc);
    const int tid = threadIdx.x;
    const int wid = tid >> 5, lane = tid & 31;
    const int t0 = blockIdx.x * 64;
    const int n  = blockIdx.y;
    const int hp = n >> 1;
    const int wr = wid & 3, wc = wid >> 2;
    const int R  = wr * 16;
    const int g = lane >> 2, t4 = lane & 3;

    const uint32_t sQh = sb, sQl = sb + QPL;
    const uint32_t sKh = sb + 2 * QPL;
    const uint32_t sKl = sKh + KPL;
    const uint32_t sV  = sKh + 2 * KPL;     // fp16 single plane
    const uint32_t sP  = sKh + 3 * KPL;     // fp16 single plane
    float* redmax = reinterpret_cast<float*>(smc + 2 * QPL + 3 * KPL + PPL);
    float* redsum = redmax + 128;

    #pragma unroll
    for (int i = 0; i < 16; i++) {
        int idx = tid + i * 256;
        int pl = idx >> 11;
        int r = (idx >> 5) & 63, c = idx & 31;
        const __nv_bfloat16* src = (pl ? g_ql : g_qh) +
            ((size_t)(t0 + r) * 16 + n) * 256 + c * 8;
        cp_async16(sb + pl * QPL + r * SROWB + c * 16, src);
    }
    cp_commit();

    auto issue_K = [&](int sc0) {
        #pragma unroll
        for (int i = 0; i < 8; i++) {
            int idx = tid + i * 256;
            int pl = idx >> 10;
            int r = (idx >> 5) & 31, c = idx & 31;
            const __nv_bfloat16* src = (pl ? g_kvl : g_kvh) +
                ((size_t)(sc0 + r) * 16 + hp) * 256 + c * 8;
            cp_async16(sKh + pl * KPL + r * SROWB + c * 16, src);
        }
    };
    auto issue_V = [&](int sc0) {
        #pragma unroll
        for (int i = 0; i < 4; i++) {
            int idx = tid + i * 256;
            int r = idx >> 5, c = idx & 31;
            const __half* src = g_v16 + ((size_t)(sc0 + r) * 8 + hp) * 256 + c * 8;
            cp_async16(sV + r * SROWB + c * 16, src);
        }
    };

    float o[16][4];
    #pragma unroll
    for (int i = 0; i < 16; i++)
        #pragma unroll
        for (int c = 0; c < 4; c++) o[i][c] = 0.f;
    float m2[2] = {-1e29f, -1e29f}, l2[2] = {0.f, 0.f};

    int s_lo = t0 - (WINDOW - 1); if (s_lo < 0) s_lo = 0; s_lo &= ~31;

    const int aoff  = (R + (lane & 7) + ((lane >> 3) & 1) * 8) * SROWB + ((lane >> 4) & 1) * 16;
    const int koff  = (((lane >> 4) & 1) * 8 + (lane & 7)) * SROWB + ((lane >> 3) & 1) * 16
                      + wc * 16 * SROWB;
    const int voff  = (((lane >> 3) & 1) * 8 + (lane & 7)) * SROWB + ((lane >> 4) & 1) * 16
                      + wc * 256;
    const int aoffP = (R + (lane & 7) + ((lane >> 3) & 1) * 8) * PROWB + ((lane >> 4) & 1) * 16;
    const int tq0 = t0 + R + g, tq1 = tq0 + 8;

    issue_K(s_lo); cp_commit();
    issue_V(s_lo); cp_commit();
    asm volatile("cp.async.wait_group 1;");
    __syncthreads();

    for (int sc0 = s_lo; sc0 <= t0 + 63; sc0 += 32) {
        const bool has_next = (sc0 + 32 <= t0 + 63);

        float s[2][4];
        #pragma unroll
        for (int j = 0; j < 2; j++)
            #pragma unroll
            for (int c = 0; c < 4; c++) s[j][c] = 0.f;

        #pragma unroll 4
        for (int hs = 0; hs < 16; hs++) {
            uint32_t qh[4], ql[4], kh[4], kl[4];
            ldsm_x4(qh[0], qh[1], qh[2], qh[3], sQh + aoff + hs * 32);
            ldsm_x4(ql[0], ql[1], ql[2], ql[3], sQl + aoff + hs * 32);
            ldsm_x4(kh[0], kh[1], kh[2], kh[3], sKh + koff + hs * 32);
            ldsm_x4(kl[0], kl[1], kl[2], kl[3], sKl + koff + hs * 32);
            mma_bf16(s[0], qh, kh); mma_bf16(s[0], qh, kl); mma_bf16(s[0], ql, kh);
            mma_bf16(s[1], qh, kh + 2); mma_bf16(s[1], qh, kl + 2); mma_bf16(s[1], ql, kh + 2);
        }

        #pragma unroll
        for (int j = 0; j < 2; j++)
            #pragma unroll
            for (int c = 0; c < 4; c++) {
                int tq = (c >> 1) ? tq1 : tq0;
                int sk = sc0 + wc * 16 + j * 8 + 2 * t4 + (c & 1);
                float xx = s[j][c] * (1.0f / SOFT_CAP);
                xx = fminf(fmaxf(xx, -10.f), 10.f);
                float e = __expf(2.0f * xx);
                float val = SOFT_CAP * __fdividef(e - 1.0f, e + 1.0f);
                bool ok = (sk <= tq) && (sk > tq - WINDOW);
                s[j][c] = ok ? val : -1e30f;
            }

        float mx0 = fmaxf(fmaxf(s[0][0], s[0][1]), fmaxf(s[1][0], s[1][1]));
        float mx1 = fmaxf(fmaxf(s[0][2], s[0][3]), fmaxf(s[1][2], s[1][3]));
        mx0 = fmaxf(mx0, __shfl_xor_sync(0xffffffffu, mx0, 1));
        mx0 = fmaxf(mx0, __shfl_xor_sync(0xffffffffu, mx0, 2));
        mx1 = fmaxf(mx1, __shfl_xor_sync(0xffffffffu, mx1, 1));
        mx1 = fmaxf(mx1, __shfl_xor_sync(0xffffffffu, mx1, 2));
        if (t4 == 0) {
            redmax[wc * 64 + R + g] = mx0;
            redmax[wc * 64 + R + g + 8] = mx1;
        }
        __syncthreads();

        if (has_next) issue_K(sc0 + 32);
        cp_commit();

        float cm0 = fmaxf(mx0, redmax[(1 - wc) * 64 + R + g]);
        float cm1 = fmaxf(mx1, redmax[(1 - wc) * 64 + R + g + 8]);
        float mn0 = fmaxf(m2[0], cm0), mn1 = fmaxf(m2[1], cm1);
        float a0 = __expf(m2[0] - mn0), a1 = __expf(m2[1] - mn1);
        m2[0] = mn0; m2[1] = mn1;

        float sum0 = 0.f, sum1 = 0.f;
        #pragma unroll
        for (int j = 0; j < 2; j++) {
            s[j][0] = __expf(s[j][0] - mn0); sum0 += s[j][0];
            s[j][1] = __expf(s[j][1] - mn0); sum0 += s[j][1];
            s[j][2] = __expf(s[j][2] - mn1); sum1 += s[j][2];
            s[j][3] = __expf(s[j][3] - mn1); sum1 += s[j][3];
        }
        sum0 += __shfl_xor_sync(0xffffffffu, sum0, 1);
        sum0 += __shfl_xor_sync(0xffffffffu, sum0, 2);
        sum1 += __shfl_xor_sync(0xffffffffu, sum1, 1);
        sum1 += __shfl_xor_sync(0xffffffffu, sum1, 2);
        if (t4 == 0) {
            redsum[wc * 64 + R + g] = sum0;
            redsum[wc * 64 + R + g + 8] = sum1;
        }

        // store P (fp16 single) for PV A-frags
        #pragma unroll
        for (int j = 0; j < 2; j++) {
            int kcol = wc * 16 + j * 8 + 2 * t4;
            *reinterpret_cast<__half2*>(smc + (sP - sb) + (R + g) * PROWB + kcol * 2) =
                __floats2half2_rn(s[j][0], s[j][1]);
            *reinterpret_cast<__half2*>(smc + (sP - sb) + (R + g + 8) * PROWB + kcol * 2) =
                __floats2half2_rn(s[j][2], s[j][3]);
        }

        cp_wait1();
        __syncthreads();

        l2[0] = l2[0] * a0 + sum0 + redsum[(1 - wc) * 64 + R + g];
        l2[1] = l2[1] * a1 + sum1 + redsum[(1 - wc) * 64 + R + g + 8];

        if (a0 != 1.f || a1 != 1.f) {
            #pragma unroll
            for (int i = 0; i < 16; i++) {
                o[i][0] *= a0; o[i][1] *= a0;
                o[i][2] *= a1; o[i][3] *= a1;
            }
        }

        // PV: fp16 single, 2 MMAs per u
        #pragma unroll
        for (int ks = 0; ks < 2; ks++) {
            uint32_t ph[4];
            ldsm_x4(ph[0], ph[1], ph[2], ph[3], sP + aoffP + ks * 32);
            #pragma unroll
            for (int u = 0; u < 8; u++) {
                uint32_t vh[4];
                ldsm_x4t(vh[0], vh[1], vh[2], vh[3], sV + voff + ks * 16 * SROWB + u * 32);
                mma_fp16(o[2 * u],     ph, vh);
                mma_fp16(o[2 * u + 1], ph, vh + 2);
            }
        }

        __syncthreads();
        if (has_next) issue_V(sc0 + 32);
        cp_commit();
        cp_wait1();
        __syncthreads();
    }

    float inv0 = __fdividef(1.f, l2[0]);
    float inv1 = __fdividef(1.f, l2[1]);
    #pragma unroll
    for (int nt = 0; nt < 16; nt++) {
        int dim = wc * 128 + nt * 8 + 2 * t4;
        float v0 = o[nt][0] * inv0, v1 = o[nt][1] * inv0;
        float v2 = o[nt][2] * inv1, v3 = o[nt][3] * inv1;
        size_t adr0 = ((size_t)tq0 * 16 + n) * 256 + dim;
        size_t adr1 = ((size_t)tq1 * 16 + n) * 256 + dim;
        *reinterpret_cast<__half2*>(g_enc16 + adr0) = __floats2half2_rn(v0, v1);
        *reinterpret_cast<__half2*>(g_enc16 + adr1) = __floats2half2_rn(v2, v3);
    }
}

// ================= launch =================
extern "C" void kernel_launch(void* const* d_in, const int* in_sizes, int n_in,
                              void* d_out, int out_size)
{
    const float* x       = (const float*)d_in[0];
    const int*   segpos  = (const int*)  d_in[1];
    const float* w_q     = (const float*)d_in[3];
    const float* w_kv    = (const float*)d_in[4];
    const float* w_out   = (const float*)d_in[5];
    const float* q_scale = (const float*)d_in[6];
    const float* k_scale = (const float*)d_in[7];
    float*       out     = (float*)d_out;

    __nv_bfloat16 *xh, *xl, *wallh, *walll;
    __half *x16, *wv16, *wo16, *enc16;
    float *gqkv;
    cudaGetSymbolAddress((void**)&xh,    g_xh);
    cudaGetSymbolAddress((void**)&xl,    g_xl);
    cudaGetSymbolAddress((void**)&x16,   g_x16);
    cudaGetSymbolAddress((void**)&wallh, g_wallh);
    cudaGetSymbolAddress((void**)&walll, g_walll);
    cudaGetSymbolAddress((void**)&wv16,  g_wv16);
    cudaGetSymbolAddress((void**)&wo16,  g_wo16);
    cudaGetSymbolAddress((void**)&enc16, g_enc16);
    cudaGetSymbolAddress((void**)&gqkv,  g_qkv);

    const dim3 blk(256);
    const size_t hslot = (size_t)HDIM * D_MODEL;

    // 0. precision prep
    convert_x_kernel<<<(T_SEQ * D_MODEL) / (256 * 4), blk>>>(x);
    transpose_conv_kernel<<<dim3(HDIM / 32, D_MODEL / 32, 16), blk>>>(
        w_q, wallh, walll, D_MODEL, HDIM);                               // q slots 0..15
    transpose_conv_kernel<<<dim3(HDIM / 32, D_MODEL / 32, 8), blk>>>(
        w_kv, wallh + 16 * hslot, walll + 16 * hslot, D_MODEL, HDIM);    // k slots 16..23
    transpose_conv_f16_kernel<<<dim3(HDIM / 32, D_MODEL / 32, 8), blk>>>(
        w_kv + 8 * hslot, wv16, D_MODEL, HDIM);                          // v weights fp16
    transpose_conv_f16_kernel<<<dim3(D_MODEL / 32, (N_HEADS * HDIM) / 32, 1), blk>>>(
        w_out, wo16, N_HEADS * HDIM, D_MODEL);

    // 1a. Q+K projection (split-bf16, 24 slots)
    cudaFuncSetAttribute(gemm_qkv_kernel, cudaFuncAttributeMaxDynamicSharedMemorySize, GEMM_SMEM_QKV);
    gemm_qkv_kernel<<<dim3(T_SEQ / Q_MT, (24 * HDIM) / Q_NT), blk, GEMM_SMEM_QKV>>>(
        xh, xl, wallh, walll, gqkv, D_MODEL, 32 * HDIM);

    // 1b. V projection (fp16 single, 8 slots -> staging cols 24*256..)
    cudaFuncSetAttribute(gemm_f16_kernel, cudaFuncAttributeMaxDynamicSharedMemorySize, GEMM_SMEM_OUT);
    gemm_f16_kernel<<<dim3(T_SEQ / O_MT, (8 * HDIM) / O_NT), blk, GEMM_SMEM_OUT>>>(
        x16, wv16, gqkv, D_MODEL, 32 * HDIM, 24 * HDIM);

    // 2. fused norms + rope
    norm_rope_all_kernel<<<(T_SEQ * 32) / 8, blk>>>(q_scale, k_scale, segpos);

    // 3. attention (QK 3-term, PV fp16)
    cudaFuncSetAttribute(attn_mma_kernel, cudaFuncAttributeMaxDynamicSharedMemorySize, ATTN_SMEM);
    attn_mma_kernel<<<dim3(T_SEQ / 64, N_HEADS), blk, ATTN_SMEM>>>();

    // 4. output projection (fp16 single)
    gemm_f16_kernel<<<dim3(T_SEQ / O_MT, D_MODEL / O_NT), blk, GEMM_SMEM_OUT>>>(
        enc16, wo16, out, N_HEADS * HDIM, D_MODEL, 0);
}

// round 15
// speedup vs baseline: 1.4977x; 1.0249x over previous
#include <cuda_runtime.h>
#include <cuda_bf16.h>
#include <cuda_fp16.h>
#include <math.h>
#include <stdint.h>

// ---------------- problem constants ----------------
#define T_SEQ   2048
#define D_MODEL 3072
#define N_HEADS 16
#define K_HEADS 8
#define HDIM    256
#define WINDOW  1024
#define SOFT_CAP 50.0f
#define EPS 1e-6f

// ---------------- scratch (static device globals) ----------------
__device__ float g_qkv[(size_t)T_SEQ * 32 * HDIM];          // [t][slot][h] q0-15,k16-23,v24-31
__device__ __nv_bfloat16 g_xh [(size_t)T_SEQ * D_MODEL];
__device__ __nv_bfloat16 g_xl [(size_t)T_SEQ * D_MODEL];
__device__ __half        g_x16[(size_t)T_SEQ * D_MODEL];
__device__ __nv_bfloat16 g_qh [(size_t)T_SEQ * N_HEADS * HDIM];
__device__ __nv_bfloat16 g_ql [(size_t)T_SEQ * N_HEADS * HDIM];
__device__ __nv_bfloat16 g_kvh[(size_t)T_SEQ * 16 * HDIM];  // K slots 0..7 used
__device__ __nv_bfloat16 g_kvl[(size_t)T_SEQ * 16 * HDIM];
__device__ __half        g_v16[(size_t)T_SEQ * 8 * HDIM];   // V fp16
__device__ __nv_bfloat16 g_wallh[(size_t)32 * HDIM * D_MODEL];  // q+k slots (24 used)
__device__ __nv_bfloat16 g_walll[(size_t)32 * HDIM * D_MODEL];
__device__ __half g_wv16 [(size_t)8 * HDIM * D_MODEL];      // V weights fp16 K-major
__device__ __half g_wo16 [(size_t)D_MODEL * N_HEADS * HDIM];
__device__ __half g_enc16[(size_t)T_SEQ * N_HEADS * HDIM];

// ---------------- low-level helpers ----------------
__device__ __forceinline__ uint32_t smem_u32(const void* p) {
    uint32_t a;
    asm("{ .reg .u64 t; cvta.to.shared.u64 t, %1; cvt.u32.u64 %0, t; }" : "=r"(a) : "l"(p));
    return a;
}
__device__ __forceinline__ void cp_async16(uint32_t dst, const void* src) {
    asm volatile("cp.async.cg.shared.global [%0], [%1], 16;" :: "r"(dst), "l"(src));
}
__device__ __forceinline__ void cp_commit() { asm volatile("cp.async.commit_group;"); }
__device__ __forceinline__ void cp_wait1()  { asm volatile("cp.async.wait_group 1;"); }
__device__ __forceinline__ void cp_wait0()  { asm volatile("cp.async.wait_group 0;"); }

__device__ __forceinline__ void ldsm_x4(uint32_t& r0, uint32_t& r1, uint32_t& r2, uint32_t& r3,
                                        uint32_t addr) {
    asm volatile("ldmatrix.sync.aligned.m8n8.x4.shared.b16 {%0,%1,%2,%3}, [%4];"
                 : "=r"(r0), "=r"(r1), "=r"(r2), "=r"(r3) : "r"(addr));
}
__device__ __forceinline__ void ldsm_x4t(uint32_t& r0, uint32_t& r1, uint32_t& r2, uint32_t& r3,
                                         uint32_t addr) {
    asm volatile("ldmatrix.sync.aligned.m8n8.x4.trans.shared.b16 {%0,%1,%2,%3}, [%4];"
                 : "=r"(r0), "=r"(r1), "=r"(r2), "=r"(r3) : "r"(addr));
}
__device__ __forceinline__ void mma_bf16(float* c, const uint32_t* a, const uint32_t* b) {
    asm volatile("mma.sync.aligned.m16n8k16.row.col.f32.bf16.bf16.f32 "
                 "{%0,%1,%2,%3},{%4,%5,%6,%7},{%8,%9},{%0,%1,%2,%3};"
                 : "+f"(c[0]), "+f"(c[1]), "+f"(c[2]), "+f"(c[3])
                 : "r"(a[0]), "r"(a[1]), "r"(a[2]), "r"(a[3]), "r"(b[0]), "r"(b[1]));
}
__device__ __forceinline__ void mma_fp16(float* c, const uint32_t* a, const uint32_t* b) {
    asm volatile("mma.sync.aligned.m16n8k16.row.col.f32.f16.f16.f32 "
                 "{%0,%1,%2,%3},{%4,%5,%6,%7},{%8,%9},{%0,%1,%2,%3};"
                 : "+f"(c[0]), "+f"(c[1]), "+f"(c[2]), "+f"(c[3])
                 : "r"(a[0]), "r"(a[1]), "r"(a[2]), "r"(a[3]), "r"(b[0]), "r"(b[1]));
}
__device__ __forceinline__ void split_bf16(float x, __nv_bfloat16& h, __nv_bfloat16& l) {
    h = __float2bfloat16(x);
    l = __float2bfloat16(x - __bfloat162float(h));
}

// ================= split-bf16 GEMM for Q+K: MT=128, NT=128, 2-stage, 2 CTAs/SM =================
#define LDHB 80
#define Q_MT 128
#define Q_NT 128
#define Q_APL (Q_MT * LDHB)           // 10240
#define Q_BPL (Q_NT * LDHB)           // 10240
#define Q_STAGE (2 * Q_APL + 2 * Q_BPL)   // 40960
#define GEMM_SMEM_QKV (2 * Q_STAGE)       // 81920 per CTA -> 2 CTAs/SM

__global__ __launch_bounds__(256, 2) void gemm_qkv_kernel(
    const __nv_bfloat16* __restrict__ Ah, const __nv_bfloat16* __restrict__ Al,
    const __nv_bfloat16* __restrict__ Bh, const __nv_bfloat16* __restrict__ Bl,
    float* __restrict__ C, int Kdim, int ldc)
{
    extern __shared__ char smem[];
    const uint32_t sbase = smem_u32(smem);
    const int tid = threadIdx.x;
    const int m0 = blockIdx.x * Q_MT, n0b = blockIdx.y * Q_NT;
    const __nv_bfloat16* Ahm = Ah + (size_t)m0 * Kdim;
    const __nv_bfloat16* Alm = Al + (size_t)m0 * Kdim;
    const __nv_bfloat16* Bhz = Bh + (size_t)n0b * Kdim;
    const __nv_bfloat16* Blz = Bl + (size_t)n0b * Kdim;
    const int NK = Kdim / 32;

    const int wid = tid >> 5, lane = tid & 31;
    const int wm = wid & 1, wn = wid >> 1;     // 2M x 4N, warp 64x32, JW=4
    const int g = lane >> 2, t4 = lane & 3;

    auto issue_stage = [&](int s, int kt) {
        const int k0 = kt * 32;
        const uint32_t stg = sbase + s * Q_STAGE;
        #pragma unroll
        for (int i = 0; i < 2; i++) {
            int idx = tid + i * 256;
            int r = idx >> 2, c = idx & 3;
            size_t goff = (size_t)r * Kdim + k0 + c * 8;
            uint32_t d = stg + r * LDHB + c * 16;
            cp_async16(d,         Ahm + goff);
            cp_async16(d + Q_APL, Alm + goff);
            uint32_t db = stg + 2 * Q_APL + r * LDHB + c * 16;
            cp_async16(db,         Bhz + goff);
            cp_async16(db + Q_BPL, Blz + goff);
        }
    };

    float acc[4][4][4];
    #pragma unroll
    for (int i = 0; i < 4; i++)
        #pragma unroll
        for (int j = 0; j < 4; j++)
            #pragma unroll
            for (int r = 0; r < 4; r++) acc[i][j][r] = 0.f;

    const int arow = wm * 64 + (lane & 7) + ((lane >> 3) & 1) * 8;
    const int akof = ((lane >> 4) & 1) * 8;
    const int brow = wn * 32 + (lane & 7) + ((lane >> 4) & 1) * 8;
    const int bkof = ((lane >> 3) & 1) * 8;

    issue_stage(0, 0); cp_commit();
    issue_stage(1, 1); cp_commit();

    for (int kt = 0; kt < NK; kt++) {
        if (kt >= NK - 1) cp_wait0(); else cp_wait1();
        __syncthreads();

        const uint32_t st = sbase + (kt & 1) * Q_STAGE;
        #pragma unroll
        for (int ks = 0; ks < 2; ks++) {
            uint32_t ah[4][4], al[4][4];
            #pragma unroll
            for (int i = 0; i < 4; i++) {
                uint32_t ad = st + (arow + i * 16) * LDHB + (ks * 16 + akof) * 2;
                ldsm_x4(ah[i][0], ah[i][1], ah[i][2], ah[i][3], ad);
                ldsm_x4(al[i][0], al[i][1], al[i][2], al[i][3], ad + Q_APL);
            }
            #pragma unroll
            for (int jp = 0; jp < 2; jp++) {
                uint32_t bd = st + 2 * Q_APL + (brow + jp * 16) * LDHB + (ks * 16 + bkof) * 2;
                uint32_t bh[4], bl[4];
                ldsm_x4(bh[0], bh[1], bh[2], bh[3], bd);
                ldsm_x4(bl[0], bl[1], bl[2], bl[3], bd + Q_BPL);
                #pragma unroll
                for (int i = 0; i < 4; i++) {
                    #pragma unroll
                    for (int jj = 0; jj < 2; jj++) {
                        const int j = 2 * jp + jj;
                        mma_bf16(acc[i][j], ah[i], bh + 2 * jj);
                        mma_bf16(acc[i][j], ah[i], bl + 2 * jj);
                        mma_bf16(acc[i][j], al[i], bh + 2 * jj);
                    }
                }
            }
        }

        __syncthreads();
        if (kt + 2 < NK) { issue_stage(kt & 1, kt + 2); cp_commit(); }
    }

    #pragma unroll
    for (int i = 0; i < 4; i++) {
        const int r0 = m0 + wm * 64 + i * 16 + g;
        #pragma unroll
        for (int j = 0; j < 4; j++) {
            const int c0 = n0b + wn * 32 + j * 8 + t4 * 2;
            *reinterpret_cast<float2*>(&C[(size_t)r0 * ldc + c0]) =
                make_float2(acc[i][j][0], acc[i][j][1]);
            *reinterpret_cast<float2*>(&C[(size_t)(r0 + 8) * ldc + c0]) =
                make_float2(acc[i][j][2], acc[i][j][3]);
        }
    }
}

// ================= single-fp16 GEMM (V projection + OUT) — unchanged R12 =================
#define O_MT 64
#define O_NT 128
#define O_APL (O_MT * LDHB)
#define O_BPL (O_NT * LDHB)
#define O_STAGE (O_APL + O_BPL)
#define GEMM_SMEM_OUT (3 * O_STAGE)   // 46080

__global__ __launch_bounds__(256) void gemm_f16_kernel(
    const __half* __restrict__ A, const __half* __restrict__ B,
    float* __restrict__ C, int Kdim, int ldc, int ccol0)
{
    extern __shared__ char smem[];
    const uint32_t sbase = smem_u32(smem);
    const int tid = threadIdx.x;
    const int m0 = blockIdx.x * O_MT, n0b = blockIdx.y * O_NT;
    const __half* Am = A + (size_t)m0 * Kdim;
    const __half* Bz = B + (size_t)n0b * Kdim;
    const int NK = Kdim / 32;

    const int wid = tid >> 5, lane = tid & 31;
    const int wn = wid;
    const int g = lane >> 2, t4 = lane & 3;

    auto issue_stage = [&](int s, int kt) {
        const int k0 = kt * 32;
        const uint32_t stg = sbase + s * O_STAGE;
        {
            int r = tid >> 2, c = tid & 3;
            cp_async16(stg + r * LDHB + c * 16, Am + (size_t)r * Kdim + k0 + c * 8);
        }
        #pragma unroll
        for (int i = 0; i < 2; i++) {
            int idx = tid + i * 256;
            int r = idx >> 2, c = idx & 3;
            cp_async16(stg + O_APL + r * LDHB + c * 16, Bz + (size_t)r * Kdim + k0 + c * 8);
        }
    };

    float acc[4][2][4];
    #pragma unroll
    for (int i = 0; i < 4; i++)
        #pragma unroll
        for (int j = 0; j < 2; j++)
            #pragma unroll
            for (int r = 0; r < 4; r++) acc[i][j][r] = 0.f;

    const int arow = (lane & 7) + ((lane >> 3) & 1) * 8;
    const int akof = ((lane >> 4) & 1) * 8;
    const int brow = wn * 16 + (lane & 7) + ((lane >> 4) & 1) * 8;
    const int bkof = ((lane >> 3) & 1) * 8;

    issue_stage(0, 0); cp_commit();
    issue_stage(1, 1); cp_commit();

    for (int kt = 0; kt < NK; kt++) {
        cp_wait1();
        __syncthreads();
        if (kt + 2 < NK) issue_stage((kt + 2) % 3, kt + 2);
        cp_commit();

        const uint32_t st = sbase + (kt % 3) * O_STAGE;
        #pragma unroll
        for (int ks = 0; ks < 2; ks++) {
            uint32_t ah[4][4];
            #pragma unroll
            for (int i = 0; i < 4; i++) {
                uint32_t ad = st + (arow + i * 16) * LDHB + (ks * 16 + akof) * 2;
                ldsm_x4(ah[i][0], ah[i][1], ah[i][2], ah[i][3], ad);
            }
            uint32_t bd = st + O_APL + brow * LDHB + (ks * 16 + bkof) * 2;
            uint32_t bh[4];
            ldsm_x4(bh[0], bh[1], bh[2], bh[3], bd);
            #pragma unroll
            for (int i = 0; i < 4; i++) {
                mma_fp16(acc[i][0], ah[i], bh);
                mma_fp16(acc[i][1], ah[i], bh + 2);
            }
        }
    }

    #pragma unroll
    for (int i = 0; i < 4; i++) {
        const int r0 = m0 + i * 16 + g;
        #pragma unroll
        for (int j = 0; j < 2; j++) {
            const int c0 = ccol0 + n0b + wn * 16 + j * 8 + t4 * 2;
            *reinterpret_cast<float2*>(&C[(size_t)r0 * ldc + c0]) =
                make_float2(acc[i][j][0], acc[i][j][1]);
            *reinterpret_cast<float2*>(&C[(size_t)(r0 + 8) * ldc + c0]) =
                make_float2(acc[i][j][2], acc[i][j][3]);
        }
    }
}

// ================= x -> bf16 hi/lo + fp16 planes =================
__global__ __launch_bounds__(256) void convert_x_kernel(const float* __restrict__ x)
{
    size_t i = ((size_t)blockIdx.x * 256 + threadIdx.x) * 4;
    float4 v = *reinterpret_cast<const float4*>(x + i);
    __nv_bfloat16 h[4], l[4];
    split_bf16(v.x, h[0], l[0]); split_bf16(v.y, h[1], l[1]);
    split_bf16(v.z, h[2], l[2]); split_bf16(v.w, h[3], l[3]);
    *reinterpret_cast<__nv_bfloat162*>(g_xh + i)     = __nv_bfloat162(h[0], h[1]);
    *reinterpret_cast<__nv_bfloat162*>(g_xh + i + 2) = __nv_bfloat162(h[2], h[3]);
    *reinterpret_cast<__nv_bfloat162*>(g_xl + i)     = __nv_bfloat162(l[0], l[1]);
    *reinterpret_cast<__nv_bfloat162*>(g_xl + i + 2) = __nv_bfloat162(l[2], l[3]);
    *reinterpret_cast<__half2*>(g_x16 + i)     = __floats2half2_rn(v.x, v.y);
    *reinterpret_cast<__half2*>(g_x16 + i + 2) = __floats2half2_rn(v.z, v.w);
}

// ================= transpose + convert (bf16 hi/lo) =================
__global__ __launch_bounds__(256) void transpose_conv_kernel(
    const float* __restrict__ in, __nv_bfloat16* __restrict__ outh,
    __nv_bfloat16* __restrict__ outl, int R, int C)
{
    __shared__ float t[32][33];
    size_t zo = (size_t)blockIdx.z * R * C;
    int c0 = blockIdx.x * 32, r0 = blockIdx.y * 32;
    int tx = threadIdx.x & 31, ty = threadIdx.x >> 5;
    #pragma unroll
    for (int i = 0; i < 32; i += 8)
        t[ty + i][tx] = in[zo + (size_t)(r0 + ty + i) * C + c0 + tx];
    __syncthreads();
    #pragma unroll
    for (int i = 0; i < 32; i += 8) {
        float v = t[tx][ty + i];
        __nv_bfloat16 h, l;
        split_bf16(v, h, l);
        size_t o = zo + (size_t)(c0 + ty + i) * R + r0 + tx;
        outh[o] = h;
        outl[o] = l;
    }
}

// ================= transpose + convert (fp16 single, z-batched) =================
__global__ __launch_bounds__(256) void transpose_conv_f16_kernel(
    const float* __restrict__ in, __half* __restrict__ outp, int R, int C)
{
    __shared__ float t[32][33];
    size_t zo = (size_t)blockIdx.z * R * C;
    int c0 = blockIdx.x * 32, r0 = blockIdx.y * 32;
    int tx = threadIdx.x & 31, ty = threadIdx.x >> 5;
    #pragma unroll
    for (int i = 0; i < 32; i += 8)
        t[ty + i][tx] = in[zo + (size_t)(r0 + ty + i) * C + c0 + tx];
    __syncthreads();
    #pragma unroll
    for (int i = 0; i < 32; i += 8)
        outp[zo + (size_t)(c0 + ty + i) * R + r0 + tx] = __float2half(t[tx][ty + i]);
}

// ================= fused RMS-norm (+scale) (+RoPE) =================
__device__ __forceinline__ void rope_apply(float v[8], int lane, int pos)
{
    #pragma unroll
    for (int j = 0; j < 4; j++) {
        int hh = lane + 32 * j;
        float ts = powf(10000.0f, (float)hh * (1.0f / 128.0f));
        float arg = (float)pos / ts;
        float sn, cs;
        sincosf(arg, &sn, &cs);
        float f = v[j], s = v[j + 4];
        v[j]     = f * cs - s * sn;
        v[j + 4] = s * cs + f * sn;
    }
}

__global__ __launch_bounds__(256) void norm_rope_all_kernel(const float* __restrict__ qscale,
                                                            const float* __restrict__ kscale,
                                                            const int* __restrict__ segpos)
{
    int row  = blockIdx.x * 8 + (threadIdx.x >> 5);   // 0..T*32-1
    int lane = threadIdx.x & 31;
    int t    = row >> 5;
    int slot = row & 31;                               // 0-15 q, 16-23 k, 24-31 v
    const float* p = g_qkv + (size_t)row * HDIM;

    float v[8]; float ss = 0.f;
    #pragma unroll
    for (int j = 0; j < 8; j++) { v[j] = p[lane + 32 * j]; ss += v[j] * v[j]; }
    #pragma unroll
    for (int o = 16; o > 0; o >>= 1) ss += __shfl_xor_sync(0xffffffffu, ss, o);
    float rstd = rsqrtf(ss * (1.0f / 256.0f) + EPS);

    if (slot < 16) {
        #pragma unroll
        for (int j = 0; j < 8; j++) {
            int h = lane + 32 * j;
            v[j] = v[j] * rstd * (1.0f + qscale[h]);
        }
        rope_apply(v, lane, segpos[t]);
        #pragma unroll
        for (int j = 0; j < 8; j++) {
            int h = lane + 32 * j;
            __nv_bfloat16 hh, ll;
            split_bf16(v[j], hh, ll);
            size_t o = ((size_t)t * 16 + slot) * HDIM + h;
            g_qh[o] = hh; g_ql[o] = ll;
        }
    } else if (slot < 24) {
        #pragma unroll
        for (int j = 0; j < 8; j++) {
            int h = lane + 32 * j;
            v[j] = v[j] * rstd * (1.0f + kscale[h]);
        }
        rope_apply(v, lane, segpos[t]);
        #pragma unroll
        for (int j = 0; j < 8; j++) {
            int h = lane + 32 * j;
            __nv_bfloat16 hh, ll;
            split_bf16(v[j], hh, ll);
            size_t o = ((size_t)t * 16 + (slot - 16)) * HDIM + h;
            g_kvh[o] = hh; g_kvl[o] = ll;
        }
    } else {
        #pragma unroll
        for (int j = 0; j < 8; j++) {
            int h = lane + 32 * j;
            g_v16[((size_t)t * 8 + (slot - 24)) * HDIM + h] = __float2half(v[j] * rstd);
        }
    }
}

// ================= tensor-core flash attention (QK 3-term, PV fp16) — unchanged R12 =================
#define SROWB 528
#define QPL 33792
#define KPL 16896
#define PROWB 80
#define PPL (64 * PROWB)
#define ATTN_SMEM (2 * QPL + 3 * KPL + PPL + 1024)   // 124416

__global__ __launch_bounds__(256, 1) void attn_mma_kernel()
{
    extern __shared__ char smc[];
    const uint32_t sb = smem_u32(smc);
    const int tid = threadIdx.x;
    const int wid = tid >> 5, lane = tid & 31;
    const int t0 = blockIdx.x * 64;
    const int n  = blockIdx.y;
    const int hp = n >> 1;
    const int wr = wid & 3, wc = wid >> 2;
    const int R  = wr * 16;
    const int g = lane >> 2, t4 = lane & 3;

    const uint32_t sQh = sb, sQl = sb + QPL;
    const uint32_t sKh = sb + 2 * QPL;
    const uint32_t sKl = sKh + KPL;
    const uint32_t sV  = sKh + 2 * KPL;
    const uint32_t sP  = sKh + 3 * KPL;
    float* redmax = reinterpret_cast<float*>(smc + 2 * QPL + 3 * KPL + PPL);
    float* redsum = redmax + 128;

    #pragma unroll
    for (int i = 0; i < 16; i++) {
        int idx = tid + i * 256;
        int pl = idx >> 11;
        int r = (idx >> 5) & 63, c = idx & 31;
        const __nv_bfloat16* src = (pl ? g_ql : g_qh) +
            ((size_t)(t0 + r) * 16 + n) * 256 + c * 8;
        cp_async16(sb + pl * QPL + r * SROWB + c * 16, src);
    }
    cp_commit();

    auto issue_K = [&](int sc0) {
        #pragma unroll
        for (int i = 0; i < 8; i++) {
            int idx = tid + i * 256;
            int pl = idx >> 10;
            int r = (idx >> 5) & 31, c = idx & 31;
            const __nv_bfloat16* src = (pl ? g_kvl : g_kvh) +
                ((size_t)(sc0 + r) * 16 + hp) * 256 + c * 8;
            cp_async16(sKh + pl * KPL + r * SROWB + c * 16, src);
        }
    };
    auto issue_V = [&](int sc0) {
        #pragma unroll
        for (int i = 0; i < 4; i++) {
            int idx = tid + i * 256;
            int r = idx >> 5, c = idx & 31;
            const __half* src = g_v16 + ((size_t)(sc0 + r) * 8 + hp) * 256 + c * 8;
            cp_async16(sV + r * SROWB + c * 16, src);
        }
    };

    float o[16][4];
    #pragma unroll
    for (int i = 0; i < 16; i++)
        #pragma unroll
        for (int c = 0; c < 4; c++) o[i][c] = 0.f;
    float m2[2] = {-1e29f, -1e29f}, l2[2] = {0.f, 0.f};

    int s_lo = t0 - (WINDOW - 1); if (s_lo < 0) s_lo = 0; s_lo &= ~31;

    const int aoff  = (R + (lane & 7) + ((lane >> 3) & 1) * 8) * SROWB + ((lane >> 4) & 1) * 16;
    const int koff  = (((lane >> 4) & 1) * 8 + (lane & 7)) * SROWB + ((lane >> 3) & 1) * 16
                      + wc * 16 * SROWB;
    const int voff  = (((lane >> 3) & 1) * 8 + (lane & 7)) * SROWB + ((lane >> 4) & 1) * 16
                      + wc * 256;
    const int aoffP = (R + (lane & 7) + ((lane >> 3) & 1) * 8) * PROWB + ((lane >> 4) & 1) * 16;
    const int tq0 = t0 + R + g, tq1 = tq0 + 8;

    issue_K(s_lo); cp_commit();
    issue_V(s_lo); cp_commit();
    asm volatile("cp.async.wait_group 1;");
    __syncthreads();

    for (int sc0 = s_lo; sc0 <= t0 + 63; sc0 += 32) {
        const bool has_next = (sc0 + 32 <= t0 + 63);

        float s[2][4];
        #pragma unroll
        for (int j = 0; j < 2; j++)
            #pragma unroll
            for (int c = 0; c < 4; c++) s[j][c] = 0.f;

        #pragma unroll 4
        for (int hs = 0; hs < 16; hs++) {
            uint32_t qh[4], ql[4], kh[4], kl[4];
            ldsm_x4(qh[0], qh[1], qh[2], qh[3], sQh + aoff + hs * 32);
            ldsm_x4(ql[0], ql[1], ql[2], ql[3], sQl + aoff + hs * 32);
            ldsm_x4(kh[0], kh[1], kh[2], kh[3], sKh + koff + hs * 32);
            ldsm_x4(kl[0], kl[1], kl[2], kl[3], sKl + koff + hs * 32);
            mma_bf16(s[0], qh, kh); mma_bf16(s[0], qh, kl); mma_bf16(s[0], ql, kh);
            mma_bf16(s[1], qh, kh + 2); mma_bf16(s[1], qh, kl + 2); mma_bf16(s[1], ql, kh + 2);
        }

        #pragma unroll
        for (int j = 0; j < 2; j++)
            #pragma unroll
            for (int c = 0; c < 4; c++) {
                int tq = (c >> 1) ? tq1 : tq0;
                int sk = sc0 + wc * 16 + j * 8 + 2 * t4 + (c & 1);
                float xx = s[j][c] * (1.0f / SOFT_CAP);
                xx = fminf(fmaxf(xx, -10.f), 10.f);
                float e = __expf(2.0f * xx);
                float val = SOFT_CAP * __fdividef(e - 1.0f, e + 1.0f);
                bool ok = (sk <= tq) && (sk > tq - WINDOW);
                s[j][c] = ok ? val : -1e30f;
            }

        float mx0 = fmaxf(fmaxf(s[0][0], s[0][1]), fmaxf(s[1][0], s[1][1]));
        float mx1 = fmaxf(fmaxf(s[0][2], s[0][3]), fmaxf(s[1][2], s[1][3]));
        mx0 = fmaxf(mx0, __shfl_xor_sync(0xffffffffu, mx0, 1));
        mx0 = fmaxf(mx0, __shfl_xor_sync(0xffffffffu, mx0, 2));
        mx1 = fmaxf(mx1, __shfl_xor_sync(0xffffffffu, mx1, 1));
        mx1 = fmaxf(mx1, __shfl_xor_sync(0xffffffffu, mx1, 2));
        if (t4 == 0) {
            redmax[wc * 64 + R + g] = mx0;
            redmax[wc * 64 + R + g + 8] = mx1;
        }
        __syncthreads();

        if (has_next) issue_K(sc0 + 32);
        cp_commit();

        float cm0 = fmaxf(mx0, redmax[(1 - wc) * 64 + R + g]);
        float cm1 = fmaxf(mx1, redmax[(1 - wc) * 64 + R + g + 8]);
        float mn0 = fmaxf(m2[0], cm0), mn1 = fmaxf(m2[1], cm1);
        float a0 = __expf(m2[0] - mn0), a1 = __expf(m2[1] - mn1);
        m2[0] = mn0; m2[1] = mn1;

        float sum0 = 0.f, sum1 = 0.f;
        #pragma unroll
        for (int j = 0; j < 2; j++) {
            s[j][0] = __expf(s[j][0] - mn0); sum0 += s[j][0];
            s[j][1] = __expf(s[j][1] - mn0); sum0 += s[j][1];
            s[j][2] = __expf(s[j][2] - mn1); sum1 += s[j][2];
            s[j][3] = __expf(s[j][3] - mn1); sum1 += s[j][3];
        }
        sum0 += __shfl_xor_sync(0xffffffffu, sum0, 1);
        sum0 += __shfl_xor_sync(0xffffffffu, sum0, 2);
        sum1 += __shfl_xor_sync(0xffffffffu, sum1, 1);
        sum1 += __shfl_xor_sync(0xffffffffu, sum1, 2);
        if (t4 == 0) {
            redsum[wc * 64 + R + g] = sum0;
            redsum[wc * 64 + R + g + 8] = sum1;
        }

        #pragma unroll
        for (int j = 0; j < 2; j++) {
            int kcol = wc * 16 + j * 8 + 2 * t4;
            *reinterpret_cast<__half2*>(smc + (sP - sb) + (R + g) * PROWB + kcol * 2) =
                __floats2half2_rn(s[j][0], s[j][1]);
            *reinterpret_cast<__half2*>(smc + (sP - sb) + (R + g + 8) * PROWB + kcol * 2) =
                __floats2half2_rn(s[j][2], s[j][3]);
        }

        cp_wait1();
        __syncthreads();

        l2[0] = l2[0] * a0 + sum0 + redsum[(1 - wc) * 64 + R + g];
        l2[1] = l2[1] * a1 + sum1 + redsum[(1 - wc) * 64 + R + g + 8];

        if (a0 != 1.f || a1 != 1.f) {
            #pragma unroll
            for (int i = 0; i < 16; i++) {
                o[i][0] *= a0; o[i][1] *= a0;
                o[i][2] *= a1; o[i][3] *= a1;
            }
        }

        #pragma unroll
        for (int ks = 0; ks < 2; ks++) {
            uint32_t ph[4];
            ldsm_x4(ph[0], ph[1], ph[2], ph[3], sP + aoffP + ks * 32);
            #pragma unroll
            for (int u = 0; u < 8; u++) {
                uint32_t vh[4];
                ldsm_x4t(vh[0], vh[1], vh[2], vh[3], sV + voff + ks * 16 * SROWB + u * 32);
                mma_fp16(o[2 * u],     ph, vh);
                mma_fp16(o[2 * u + 1], ph, vh + 2);
            }
        }

        __syncthreads();
        if (has_next) issue_V(sc0 + 32);
        cp_commit();
        cp_wait1();
        __syncthreads();
    }

    float inv0 = __fdividef(1.f, l2[0]);
    float inv1 = __fdividef(1.f, l2[1]);
    #pragma unroll
    for (int nt = 0; nt < 16; nt++) {
        int dim = wc * 128 + nt * 8 + 2 * t4;
        float v0 = o[nt][0] * inv0, v1 = o[nt][1] * inv0;
        float v2 = o[nt][2] * inv1, v3 = o[nt][3] * inv1;
        size_t adr0 = ((size_t)tq0 * 16 + n) * 256 + dim;
        size_t adr1 = ((size_t)tq1 * 16 + n) * 256 + dim;
        *reinterpret_cast<__half2*>(g_enc16 + adr0) = __floats2half2_rn(v0, v1);
        *reinterpret_cast<__half2*>(g_enc16 + adr1) = __floats2half2_rn(v2, v3);
    }
}

// ================= launch =================
extern "C" void kernel_launch(void* const* d_in, const int* in_sizes, int n_in,
                              void* d_out, int out_size)
{
    const float* x       = (const float*)d_in[0];
    const int*   segpos  = (const int*)  d_in[1];
    const float* w_q     = (const float*)d_in[3];
    const float* w_kv    = (const float*)d_in[4];
    const float* w_out   = (const float*)d_in[5];
    const float* q_scale = (const float*)d_in[6];
    const float* k_scale = (const float*)d_in[7];
    float*       out     = (float*)d_out;

    __nv_bfloat16 *xh, *xl, *wallh, *walll;
    __half *x16, *wv16, *wo16, *enc16;
    float *gqkv;
    cudaGetSymbolAddress((void**)&xh,    g_xh);
    cudaGetSymbolAddress((void**)&xl,    g_xl);
    cudaGetSymbolAddress((void**)&x16,   g_x16);
    cudaGetSymbolAddress((void**)&wallh, g_wallh);
    cudaGetSymbolAddress((void**)&walll, g_walll);
    cudaGetSymbolAddress((void**)&wv16,  g_wv16);
    cudaGetSymbolAddress((void**)&wo16,  g_wo16);
    cudaGetSymbolAddress((void**)&enc16, g_enc16);
    cudaGetSymbolAddress((void**)&gqkv,  g_qkv);

    const dim3 blk(256);
    const size_t hslot = (size_t)HDIM * D_MODEL;

    // 0. precision prep
    convert_x_kernel<<<(T_SEQ * D_MODEL) / (256 * 4), blk>>>(x);
    transpose_conv_kernel<<<dim3(HDIM / 32, D_MODEL / 32, 16), blk>>>(
        w_q, wallh, walll, D_MODEL, HDIM);                               // q slots 0..15
    transpose_conv_kernel<<<dim3(HDIM / 32, D_MODEL / 32, 8), blk>>>(
        w_kv, wallh + 16 * hslot, walll + 16 * hslot, D_MODEL, HDIM);    // k slots 16..23
    transpose_conv_f16_kernel<<<dim3(HDIM / 32, D_MODEL / 32, 8), blk>>>(
        w_kv + 8 * hslot, wv16, D_MODEL, HDIM);                          // v weights fp16
    transpose_conv_f16_kernel<<<dim3(D_MODEL / 32, (N_HEADS * HDIM) / 32, 1), blk>>>(
        w_out, wo16, N_HEADS * HDIM, D_MODEL);

    // 1a. Q+K projection (split-bf16, MT=128/NT=128, 2-stage, 2 CTAs/SM)
    cudaFuncSetAttribute(gemm_qkv_kernel, cudaFuncAttributeMaxDynamicSharedMemorySize, GEMM_SMEM_QKV);
    gemm_qkv_kernel<<<dim3(T_SEQ / Q_MT, (24 * HDIM) / Q_NT), blk, GEMM_SMEM_QKV>>>(
        xh, xl, wallh, walll, gqkv, D_MODEL, 32 * HDIM);

    // 1b. V projection (fp16 single, 8 slots -> staging cols 24*256..)
    cudaFuncSetAttribute(gemm_f16_kernel, cudaFuncAttributeMaxDynamicSharedMemorySize, GEMM_SMEM_OUT);
    gemm_f16_kernel<<<dim3(T_SEQ / O_MT, (8 * HDIM) / O_NT), blk, GEMM_SMEM_OUT>>>(
        x16, wv16, gqkv, D_MODEL, 32 * HDIM, 24 * HDIM);

    // 2. fused norms + rope
    norm_rope_all_kernel<<<(T_SEQ * 32) / 8, blk>>>(q_scale, k_scale, segpos);

    // 3. attention (QK 3-term, PV fp16)
    cudaFuncSetAttribute(attn_mma_kernel, cudaFuncAttributeMaxDynamicSharedMemorySize, ATTN_SMEM);
    attn_mma_kernel<<<dim3(T_SEQ / 64, N_HEADS), blk, ATTN_SMEM>>>();

    // 4. output projection (fp16 single)
    gemm_f16_kernel<<<dim3(T_SEQ / O_MT, D_MODEL / O_NT), blk, GEMM_SMEM_OUT>>>(
        enc16, wo16, out, N_HEADS * HDIM, D_MODEL, 0);
}